// round 12
// baseline (speedup 1.0000x reference)
#include <cuda_runtime.h>
#include <cstddef>
#include <cstdint>

// Problem constants
#define BB   128     // batch
#define TT   512     // seq len
#define EE   256     // embed dim
#define HH   256     // hidden
#define G4H  1024    // 4*H
#define VV   32000   // vocab
#define NC   32      // classes

typedef unsigned long long ull;

// ---------------- device scratch (no allocations allowed) ----------------
__device__ float g_P[(size_t)VV * 2048];       // [V][2*4H] vocab projection
__device__ float g_hx[16][2][HH][16];          // [group][buf][hcol][row] h exchange
__device__ float g_hfinT[2][HH][BB];           // final hidden per direction, transposed
__device__ int   g_ctr[16 * 32];               // per-group barrier counters (128B apart)

// ---------------- f32x2 helpers ----------------
__device__ __forceinline__ ull pack2(float lo, float hi) {
    ull r;
    asm("mov.b64 %0, {%1, %2};" : "=l"(r) : "f"(lo), "f"(hi));
    return r;
}
__device__ __forceinline__ float2 unpack2(ull v) {
    float2 r;
    asm("mov.b64 {%0, %1}, %2;" : "=f"(r.x), "=f"(r.y) : "l"(v));
    return r;
}
__device__ __forceinline__ void ffma2(ull& d, ull a, ull b) {
    asm("fma.rn.f32x2 %0, %1, %2, %0;" : "+l"(d) : "l"(a), "l"(b));
}
__device__ __forceinline__ void addf2(ull& d, ull a) {
    asm("add.rn.f32x2 %0, %0, %1;" : "+l"(d) : "l"(a));
}

__device__ __forceinline__ int ld_acq(const int* p) {
    int v;
    asm volatile("ld.acquire.gpu.b32 %0, [%1];" : "=r"(v) : "l"(p));
    return v;
}
__device__ __forceinline__ void atom_add_rel(int* p) {
    unsigned int old;
    asm volatile("atom.add.release.gpu.u32 %0, [%1], 1;" : "=r"(old) : "l"(p) : "memory");
}

__device__ __forceinline__ float sigm(float x) { return 1.0f / (1.0f + expf(-x)); }

__device__ __forceinline__ void cpasync16(uint32_t dst, const void* src) {
    asm volatile("cp.async.cg.shared.global [%0], [%1], 16;" :: "r"(dst), "l"(src) : "memory");
}
__device__ __forceinline__ void cp_commit() {
    asm volatile("cp.async.commit_group;" ::: "memory");
}
template<int N> __device__ __forceinline__ void cp_wait() {
    asm volatile("cp.async.wait_group %0;" :: "n"(N) : "memory");
}

// =====================================================================
// Kernel A: P[v, d*1024+g] = sum_e emb[v,e] * W{f,b}[e,g] + b{f,b}[g]
// CTA tile 128x128, thread tile 8x8 (32 FFMA2/k vs 18 other instr ->
// FMA-bound), 2-stage cp.async double buffer. 32KB static smem.
// Also resets group barrier counters for kernel B.
// =====================================================================
__global__ void __launch_bounds__(256) proj_kernel(
    const float* __restrict__ emb,
    const float* __restrict__ Wf, const float* __restrict__ bf,
    const float* __restrict__ Wb, const float* __restrict__ bb)
{
    if (blockIdx.x == 0 && blockIdx.y == 0 && threadIdx.x < 16)
        g_ctr[threadIdx.x * 32] = 0;

    __shared__ float As[2][128][16];   // [stage][m][k]
    __shared__ float Bs[2][16][128];   // [stage][k][n]

    const int tid = threadIdx.x;
    const int tx = tid & 15, ty = tid >> 4;
    const int m0 = ty * 8, n0 = tx * 8;
    const int vbase = blockIdx.y * 128;
    const int nbase = blockIdx.x * 128;
    const int d = nbase >> 10;
    const float* W    = d ? Wb : Wf;
    const float* bias = d ? bb : bf;
    const int gbase = nbase & 1023;

    const uint32_t asA = (uint32_t)__cvta_generic_to_shared(&As[0][0][0]);
    const uint32_t asB = (uint32_t)__cvta_generic_to_shared(&Bs[0][0][0]);

    // copy coordinates: A tile 128x16 = 512 chunks of 16B, B tile 16x128 = 512
    const int ar0 = tid >> 2,        aq0 = tid & 3;          // chunks tid
    const int ar1 = (tid + 256) >> 2, aq1 = tid & 3;         // chunk tid+256
    const int bk0 = tid >> 5,        bo0 = tid & 31;
    const int bk1 = (tid + 256) >> 5, bo1 = tid & 31;

    ull acc[8][4] = {};

    // issue stage 0
    cpasync16(asA + (uint32_t)((ar0 * 16 + aq0 * 4) * 4),
              emb + (size_t)(vbase + ar0) * EE + aq0 * 4);
    cpasync16(asA + (uint32_t)((ar1 * 16 + aq1 * 4) * 4),
              emb + (size_t)(vbase + ar1) * EE + aq1 * 4);
    cpasync16(asB + (uint32_t)((bk0 * 128 + bo0 * 4) * 4),
              W + (size_t)bk0 * G4H + gbase + bo0 * 4);
    cpasync16(asB + (uint32_t)((bk1 * 128 + bo1 * 4) * 4),
              W + (size_t)bk1 * G4H + gbase + bo1 * 4);
    cp_commit();

    for (int s = 0; s < 16; s++) {
        if (s + 1 < 16) {
            const int b = (s + 1) & 1;
            const uint32_t aoff = (uint32_t)(b * 8192);
            cpasync16(asA + aoff + (uint32_t)((ar0 * 16 + aq0 * 4) * 4),
                      emb + (size_t)(vbase + ar0) * EE + (s + 1) * 16 + aq0 * 4);
            cpasync16(asA + aoff + (uint32_t)((ar1 * 16 + aq1 * 4) * 4),
                      emb + (size_t)(vbase + ar1) * EE + (s + 1) * 16 + aq1 * 4);
            cpasync16(asB + aoff + (uint32_t)((bk0 * 128 + bo0 * 4) * 4),
                      W + (size_t)((s + 1) * 16 + bk0) * G4H + gbase + bo0 * 4);
            cpasync16(asB + aoff + (uint32_t)((bk1 * 128 + bo1 * 4) * 4),
                      W + (size_t)((s + 1) * 16 + bk1) * G4H + gbase + bo1 * 4);
            cp_commit();
            cp_wait<1>();
        } else {
            cp_wait<0>();
        }
        __syncthreads();

        const int b = s & 1;
        #pragma unroll
        for (int k = 0; k < 16; k++) {
            ulonglong2 b01 = *(const ulonglong2*)&Bs[b][k][n0];
            ulonglong2 b23 = *(const ulonglong2*)&Bs[b][k][n0 + 4];
            #pragma unroll
            for (int i = 0; i < 8; i++) {
                float av = As[b][m0 + i][k];
                ull ad = pack2(av, av);
                ffma2(acc[i][0], ad, b01.x);
                ffma2(acc[i][1], ad, b01.y);
                ffma2(acc[i][2], ad, b23.x);
                ffma2(acc[i][3], ad, b23.y);
            }
        }
        __syncthreads();
    }

    #pragma unroll
    for (int i = 0; i < 8; i++) {
        int v = vbase + m0 + i;
        #pragma unroll
        for (int p = 0; p < 4; p++) {
            float2 va = unpack2(acc[i][p]);
            int cc = n0 + 2 * p;
            va.x += bias[gbase + cc];
            va.y += bias[gbase + cc + 1];
            *(float2*)&g_P[(size_t)v * 2048 + nbase + cc] = va;
        }
    }
}

// =====================================================================
// Kernel B: register-tiled 8-way-k-split LSTM (unchanged from R11 best).
// =====================================================================
#define UP_BYTES   131072                     // [256 k][32 hcol] ulonglong2
#define HR_BYTES   32768                      // [2 buf][256 k][16 row] float
#define RED_STRIDE 19                         // ull per thread row (16 + pad)
#define RED_BYTES  (256 * RED_STRIDE * 8)     // 38912
#define LSTM_SMEM_BYTES (UP_BYTES + HR_BYTES + RED_BYTES)   // 202752

__global__ void __launch_bounds__(256) lstm_kernel(
    const int* __restrict__ tokens,
    const float* __restrict__ Uf, const float* __restrict__ Ub)
{
    extern __shared__ char smraw[];
    ulonglong2* Up = (ulonglong2*)smraw;                     // [256 k][32 hcol]
    float* hraw = (float*)(smraw + UP_BYTES);                // [2][256][16]
    ull* red = (ull*)(smraw + UP_BYTES + HR_BYTES);          // [256 thr][19]
    const uint32_t hraw_addr = (uint32_t)__cvta_generic_to_shared(hraw);

    const int tid = threadIdx.x;
    const int gr  = blockIdx.x >> 3;              // group 0..15
    const int c   = blockIdx.x & 7;               // rank in group
    const int d   = gr >> 3;                      // direction
    const int rb  = (gr & 7) * 16;                // batch row base
    const float* U = d ? Ub : Uf;

    const int w    = tid >> 5;                    // warp -> k-slice [32w,32w+32)
    const int lane = tid & 31;
    const int rg   = lane & 1;                    // rows 8rg..8rg+7
    const int cg   = lane >> 1;                   // hcols {cg, cg+16}

    // final-tile identity (post-reduction)
    const int jf = tid & 31;                      // hcol within CTA
    const int q  = tid >> 5;                      // rows {2q, 2q+1}
    const int ghcol = c * 32 + jf;

    // Token dtype guard (jnp.int64 silently x32 in JAX unless x64 enabled).
    const bool is64 = ((tokens[1] | tokens[3] | tokens[5] | tokens[7]) == 0);
    const int ts = is64 ? 2 : 1;

    // Load U: Up[k][j] = { (u_i,u_f), (u_g,u_o) } at hcol c*32+j
    for (int i = tid; i < 8192; i += 256) {
        int k = i >> 5, j = i & 31;
        const float* ub = U + (size_t)k * G4H + c * 32 + j;
        ulonglong2 e;
        e.x = pack2(ub[0],   ub[256]);
        e.y = pack2(ub[512], ub[768]);
        Up[k * 32 + j] = e;
    }
    // zero both h buffers (h(-1) = 0)
    for (int i = tid; i < 8192; i += 256) hraw[i] = 0.f;
    __syncthreads();

    const int* tr0 = tokens + (size_t)(rb + 2 * q + 0) * TT * ts;
    const int* tr1 = tokens + (size_t)(rb + 2 * q + 1) * TT * ts;
    int* ctr = &g_ctr[gr * 32];

    // prefetch tokens for t = 0
    int te0 = d ? (TT - 1) : 0;
    int tk0 = tr0[te0 * ts], tk1 = tr1[te0 * ts];

    float cs0 = 0.f, cs1 = 0.f;

    // gather constants
    const int lane_src = 2 * (jf & 15) + (q >> 2);
    const int idx0 = ((2 * q) & 7) * 2 + (jf >> 4);

    for (int t = 0; t < TT; t++) {
        const int buf = t & 1;

        // ---- P loads for this step (consumed after reduction) ----
        int tv0 = (tk0 >= 0 && tk0 < VV) ? tk0 : 0;
        int tv1 = (tk1 >= 0 && tk1 < VV) ? tk1 : 0;
        const float* Pb0 = g_P + (size_t)tv0 * 2048 + d * 1024 + ghcol;
        const float* Pb1 = g_P + (size_t)tv1 * 2048 + d * 1024 + ghcol;
        float p00 = Pb0[0], p01 = Pb0[256], p02 = Pb0[512], p03 = Pb0[768];
        float p10 = Pb1[0], p11 = Pb1[256], p12 = Pb1[512], p13 = Pb1[768];

        // prefetch tokens for t+1
        if (t + 1 < TT) {
            int te = d ? (TT - 2 - t) : (t + 1);
            tk0 = tr0[te * ts]; tk1 = tr1[te * ts];
        }

        if (t > 0) { cp_wait<0>(); __syncthreads(); }   // h(t-1) staged

        // ---- k-loop over this warp's 32-k slice ----
        const float* hb = hraw + buf * 4096;
        const ulonglong2* ub2 = Up + cg;
        ull aIF[8][2] = {}, aGO[8][2] = {};
        const int kbeg = w * 32;
        #pragma unroll 8
        for (int k = kbeg; k < kbeg + 32; k++) {
            float4 hA = *(const float4*)(hb + k * 16 + 8 * rg);
            float4 hB = *(const float4*)(hb + k * 16 + 8 * rg + 4);
            ulonglong2 uA = ub2[k * 32];         // hcol cg
            ulonglong2 uB = ub2[k * 32 + 16];    // hcol cg+16
            ull hd0 = pack2(hA.x, hA.x), hd1 = pack2(hA.y, hA.y);
            ull hd2 = pack2(hA.z, hA.z), hd3 = pack2(hA.w, hA.w);
            ull hd4 = pack2(hB.x, hB.x), hd5 = pack2(hB.y, hB.y);
            ull hd6 = pack2(hB.z, hB.z), hd7 = pack2(hB.w, hB.w);
            ffma2(aIF[0][0], hd0, uA.x); ffma2(aGO[0][0], hd0, uA.y);
            ffma2(aIF[0][1], hd0, uB.x); ffma2(aGO[0][1], hd0, uB.y);
            ffma2(aIF[1][0], hd1, uA.x); ffma2(aGO[1][0], hd1, uA.y);
            ffma2(aIF[1][1], hd1, uB.x); ffma2(aGO[1][1], hd1, uB.y);
            ffma2(aIF[2][0], hd2, uA.x); ffma2(aGO[2][0], hd2, uA.y);
            ffma2(aIF[2][1], hd2, uB.x); ffma2(aGO[2][1], hd2, uB.y);
            ffma2(aIF[3][0], hd3, uA.x); ffma2(aGO[3][0], hd3, uA.y);
            ffma2(aIF[3][1], hd3, uB.x); ffma2(aGO[3][1], hd3, uB.y);
            ffma2(aIF[4][0], hd4, uA.x); ffma2(aGO[4][0], hd4, uA.y);
            ffma2(aIF[4][1], hd4, uB.x); ffma2(aGO[4][1], hd4, uB.y);
            ffma2(aIF[5][0], hd5, uA.x); ffma2(aGO[5][0], hd5, uA.y);
            ffma2(aIF[5][1], hd5, uB.x); ffma2(aGO[5][1], hd5, uB.y);
            ffma2(aIF[6][0], hd6, uA.x); ffma2(aGO[6][0], hd6, uA.y);
            ffma2(aIF[6][1], hd6, uB.x); ffma2(aGO[6][1], hd6, uB.y);
            ffma2(aIF[7][0], hd7, uA.x); ffma2(aGO[7][0], hd7, uA.y);
            ffma2(aIF[7][1], hd7, uB.x); ffma2(aGO[7][1], hd7, uB.y);
        }

        ull* myred = red + tid * RED_STRIDE;

        // ---- reduction pass 1: IF ----
        #pragma unroll
        for (int i = 0; i < 8; i++) {
            myred[2 * i]     = aIF[i][0];
            myred[2 * i + 1] = aIF[i][1];
        }
        __syncthreads();
        ull zIF0 = 0ull, zIF1 = 0ull;
        #pragma unroll
        for (int w8 = 0; w8 < 8; w8++) {
            const ull* pr = red + (w8 * 32 + lane_src) * RED_STRIDE;
            addf2(zIF0, pr[idx0]);
            addf2(zIF1, pr[idx0 + 2]);
        }
        __syncthreads();

        // ---- reduction pass 2: GO ----
        #pragma unroll
        for (int i = 0; i < 8; i++) {
            myred[2 * i]     = aGO[i][0];
            myred[2 * i + 1] = aGO[i][1];
        }
        __syncthreads();
        ull zGO0 = 0ull, zGO1 = 0ull;
        #pragma unroll
        for (int w8 = 0; w8 < 8; w8++) {
            const ull* pr = red + (w8 * 32 + lane_src) * RED_STRIDE;
            addf2(zGO0, pr[idx0]);
            addf2(zGO1, pr[idx0 + 2]);
        }

        // ---- activation (rows 2q, 2q+1; hcol jf) ----
        float2 vIF0 = unpack2(zIF0), vGO0 = unpack2(zGO0);
        float2 vIF1 = unpack2(zIF1), vGO1 = unpack2(zGO1);
        float i0 = sigm(vIF0.x + p00), f0 = sigm(vIF0.y + p01);
        float g0 = tanhf(vGO0.x + p02), o0 = sigm(vGO0.y + p03);
        float i1 = sigm(vIF1.x + p10), f1 = sigm(vIF1.y + p11);
        float g1 = tanhf(vGO1.x + p12), o1 = sigm(vGO1.y + p13);
        cs0 = f0 * cs0 + i0 * g0;
        cs1 = f1 * cs1 + i1 * g1;
        float h0 = o0 * tanhf(cs0);
        float h1 = o1 * tanhf(cs1);

        if (t == TT - 1) {
            *(float2*)&g_hfinT[d][ghcol][rb + 2 * q] = make_float2(h0, h1);
        } else {
            const int nb = buf ^ 1;
            *(float2*)&g_hx[gr][nb][ghcol][2 * q] = make_float2(h0, h1);
            __syncthreads();                       // all CTA stores issued
            if (tid == 0) {
                atom_add_rel(ctr);                 // release: publishes CTA's h
                const int target = 8 * (t + 1);
                while (ld_acq(ctr) < target) { }
            }
            __syncthreads();
            // stage full group h(t) (16 KB) into SMEM buffer nb
            const char* src = (const char*)&g_hx[gr][nb][0][0];
            const uint32_t dbase = hraw_addr + (uint32_t)nb * 16384;
            #pragma unroll
            for (int qq = 0; qq < 4; qq++) {
                int f = tid + qq * 256;
                cpasync16(dbase + (uint32_t)f * 16, src + (size_t)f * 16);
            }
            cp_commit();
        }
    }
}

// =====================================================================
// Kernel C: head.  h1 = relu([hf|hb] @ W1 + b1); out = softmax(h1 @ W2 + b2)
// =====================================================================
__global__ void __launch_bounds__(256) head_kernel(
    const float* __restrict__ W1, const float* __restrict__ b1,
    const float* __restrict__ W2, const float* __restrict__ b2,
    float* __restrict__ out)
{
    __shared__ float hc[8][512];
    __shared__ float h1[8][256];

    const int tid = threadIdx.x;
    const int rb = blockIdx.x * 8;

    for (int i = tid; i < 4096; i += 256) {
        int rr = i >> 9, k = i & 511;
        int dd = k >> 8, kk = k & 255;
        hc[rr][k] = g_hfinT[dd][kk][rb + rr];
    }
    __syncthreads();

    const int jj = tid;
    float acc[8] = {0.f, 0.f, 0.f, 0.f, 0.f, 0.f, 0.f, 0.f};
    for (int k = 0; k < 512; k++) {
        float wv = W1[(size_t)k * HH + jj];
        #pragma unroll
        for (int rr = 0; rr < 8; rr++) acc[rr] += hc[rr][k] * wv;
    }
    float bj = b1[jj];
    #pragma unroll
    for (int rr = 0; rr < 8; rr++) h1[rr][jj] = fmaxf(acc[rr] + bj, 0.f);
    __syncthreads();

    const int rr = tid >> 5, cc = tid & 31;
    float l = b2[cc];
    for (int k = 0; k < HH; k++) l += h1[rr][k] * W2[(size_t)k * NC + cc];

    float m = l;
    #pragma unroll
    for (int o = 16; o > 0; o >>= 1) m = fmaxf(m, __shfl_xor_sync(0xffffffffu, m, o));
    float e = expf(l - m);
    float ssum = e;
    #pragma unroll
    for (int o = 16; o > 0; o >>= 1) ssum += __shfl_xor_sync(0xffffffffu, ssum, o);
    out[(size_t)(rb + rr) * NC + cc] = e / ssum;
}

// =====================================================================
extern "C" void kernel_launch(void* const* d_in, const int* in_sizes, int n_in,
                              void* d_out, int out_size)
{
    const int*   tokens = (const int*)d_in[0];
    const float* emb = (const float*)d_in[1];
    const float* Wf  = (const float*)d_in[2];
    const float* Uf  = (const float*)d_in[3];
    const float* bf  = (const float*)d_in[4];
    const float* Wb  = (const float*)d_in[5];
    const float* Ub  = (const float*)d_in[6];
    const float* bb  = (const float*)d_in[7];
    const float* W1  = (const float*)d_in[8];
    const float* b1  = (const float*)d_in[9];
    const float* W2  = (const float*)d_in[10];
    const float* b2  = (const float*)d_in[11];
    float* out = (float*)d_out;

    cudaFuncSetAttribute(lstm_kernel, cudaFuncAttributeMaxDynamicSharedMemorySize, LSTM_SMEM_BYTES);

    proj_kernel<<<dim3(16, 250), 256>>>(emb, Wf, bf, Wb, bb);
    lstm_kernel<<<128, 256, LSTM_SMEM_BYTES>>>(tokens, Uf, Ub);
    head_kernel<<<16, 256>>>(W1, b1, W2, b2, out);
}

// round 13
// speedup vs baseline: 1.0492x; 1.0492x over previous
#include <cuda_runtime.h>
#include <cstddef>
#include <cstdint>

// Problem constants
#define BB   128     // batch
#define TT   512     // seq len
#define EE   256     // embed dim
#define HH   256     // hidden
#define G4H  1024    // 4*H
#define VV   32000   // vocab
#define NC   32      // classes

typedef unsigned long long ull;

// ---------------- device scratch (no allocations allowed) ----------------
__device__ float g_P[(size_t)VV * 2048];       // [V][2*4H] vocab projection
__device__ float g_hx[16][2][HH][16];          // [group][parity][hcol][row] h exchange
__device__ float g_hfinT[2][HH][BB];           // final hidden per direction, transposed
__device__ int   g_flag[16][8][32];            // per-(group,CTA) release flags, 128B lines

// ---------------- f32x2 helpers ----------------
__device__ __forceinline__ ull pack2(float lo, float hi) {
    ull r;
    asm("mov.b64 %0, {%1, %2};" : "=l"(r) : "f"(lo), "f"(hi));
    return r;
}
__device__ __forceinline__ float2 unpack2(ull v) {
    float2 r;
    asm("mov.b64 {%0, %1}, %2;" : "=f"(r.x), "=f"(r.y) : "l"(v));
    return r;
}
__device__ __forceinline__ void ffma2(ull& d, ull a, ull b) {
    asm("fma.rn.f32x2 %0, %1, %2, %0;" : "+l"(d) : "l"(a), "l"(b));
}
__device__ __forceinline__ void addf2(ull& d, ull a) {
    asm("add.rn.f32x2 %0, %0, %1;" : "+l"(d) : "l"(a));
}

__device__ __forceinline__ int ld_acq(const int* p) {
    int v;
    asm volatile("ld.acquire.gpu.b32 %0, [%1];" : "=r"(v) : "l"(p));
    return v;
}
__device__ __forceinline__ void st_rel(int* p, int v) {
    asm volatile("st.release.gpu.b32 [%0], %1;" :: "l"(p), "r"(v) : "memory");
}

__device__ __forceinline__ float sigm(float x) { return 1.0f / (1.0f + expf(-x)); }

__device__ __forceinline__ void cpasync16(uint32_t dst, const void* src) {
    asm volatile("cp.async.cg.shared.global [%0], [%1], 16;" :: "r"(dst), "l"(src) : "memory");
}
__device__ __forceinline__ void cp_commit() {
    asm volatile("cp.async.commit_group;" ::: "memory");
}
template<int N> __device__ __forceinline__ void cp_wait() {
    asm volatile("cp.async.wait_group %0;" :: "n"(N) : "memory");
}

// =====================================================================
// Kernel A: P[v, d*1024+g] = sum_e emb[v,e] * W{f,b}[e,g] + b{f,b}[g]
// EXACT R11 version (measured 759us). Also resets exchange flags.
// =====================================================================
__global__ void __launch_bounds__(256) proj_kernel(
    const float* __restrict__ emb,
    const float* __restrict__ Wf, const float* __restrict__ bf,
    const float* __restrict__ Wb, const float* __restrict__ bb)
{
    if (blockIdx.x == 0 && blockIdx.y == 0 && threadIdx.x < 128)
        g_flag[threadIdx.x >> 3][threadIdx.x & 7][0] = 0;

    __shared__ float As[2][64][16];   // [stage][m][k] raw A
    __shared__ float Bs[2][16][64];   // [stage][k][n] raw B

    const int tid = threadIdx.x;
    const int tx = tid & 15, ty = tid >> 4;
    const int m0 = ty * 4, n0 = tx * 4;
    const int vbase = blockIdx.y * 64;
    const int nbase = blockIdx.x * 64;
    const int d = nbase >> 10;
    const float* W    = d ? Wb : Wf;
    const float* bias = d ? bb : bf;
    const int gbase = nbase & 1023;

    const uint32_t asA = (uint32_t)__cvta_generic_to_shared(&As[0][0][0]);
    const uint32_t asB = (uint32_t)__cvta_generic_to_shared(&Bs[0][0][0]);

    const int ar = tid >> 2, aq = tid & 3;     // A: row, k-quad
    const int br = tid >> 4, bsg = tid & 15;   // B: k-row, col-quad

    ull acc[4][2] = {};

    {
        cpasync16(asA + (uint32_t)((ar * 16 + aq * 4) * 4),
                  emb + (size_t)(vbase + ar) * EE + aq * 4);
        cpasync16(asB + (uint32_t)((br * 64 + bsg * 4) * 4),
                  W + (size_t)br * G4H + gbase + bsg * 4);
        cp_commit();
    }

    for (int s = 0; s < 16; s++) {
        if (s + 1 < 16) {
            int b = (s + 1) & 1;
            cpasync16(asA + (uint32_t)(b * 4096 + (ar * 16 + aq * 4) * 4),
                      emb + (size_t)(vbase + ar) * EE + (s + 1) * 16 + aq * 4);
            cpasync16(asB + (uint32_t)(b * 4096 + (br * 64 + bsg * 4) * 4),
                      W + (size_t)((s + 1) * 16 + br) * G4H + gbase + bsg * 4);
            cp_commit();
            cp_wait<1>();
        } else {
            cp_wait<0>();
        }
        __syncthreads();

        const int b = s & 1;
        #pragma unroll
        for (int k = 0; k < 16; k++) {
            float a0 = As[b][m0 + 0][k];
            float a1 = As[b][m0 + 1][k];
            float a2 = As[b][m0 + 2][k];
            float a3 = As[b][m0 + 3][k];
            ulonglong2 bb2 = *(const ulonglong2*)&Bs[b][k][n0];
            ull ad0 = pack2(a0, a0), ad1 = pack2(a1, a1);
            ull ad2 = pack2(a2, a2), ad3 = pack2(a3, a3);
            ffma2(acc[0][0], ad0, bb2.x); ffma2(acc[0][1], ad0, bb2.y);
            ffma2(acc[1][0], ad1, bb2.x); ffma2(acc[1][1], ad1, bb2.y);
            ffma2(acc[2][0], ad2, bb2.x); ffma2(acc[2][1], ad2, bb2.y);
            ffma2(acc[3][0], ad3, bb2.x); ffma2(acc[3][1], ad3, bb2.y);
        }
        __syncthreads();
    }

    #pragma unroll
    for (int i = 0; i < 4; i++) {
        int v = vbase + m0 + i;
        #pragma unroll
        for (int p = 0; p < 2; p++) {
            float2 va = unpack2(acc[i][p]);
            int cc = n0 + 2 * p;
            va.x += bias[gbase + cc];
            va.y += bias[gbase + cc + 1];
            *(float2*)&g_P[(size_t)v * 2048 + nbase + cc] = va;
        }
    }
}

// =====================================================================
// Kernel B: register-tiled 8-way-k-split LSTM, PER-WARP flag exchange.
//
// Warp w consumes exactly CTA-rank-w's h slice (k in [32w, 32w+32)):
// each warp acquire-polls peer w's flag, cp.asyncs its 2KB slice, then
// computes — no group barrier, skew absorbed per warp. g_hx double-
// buffered by step parity (safe: data dependency bounds skew to 1 step).
// hraw is a single 16KB buffer (slice w touched only by warp w).
// k-loop/reduction/activation identical to the measured R11 core.
// =====================================================================
#define UP_BYTES   131072                     // [256 k][32 hcol] ulonglong2
#define HR_BYTES   16384                      // [256 k][16 row] float, single buf
#define RED_STRIDE 19                         // ull per thread row (16 + pad)
#define RED_BYTES  (256 * RED_STRIDE * 8)     // 38912
#define LSTM_SMEM_BYTES (UP_BYTES + HR_BYTES + RED_BYTES)   // 186368

__global__ void __launch_bounds__(256) lstm_kernel(
    const int* __restrict__ tokens,
    const float* __restrict__ Uf, const float* __restrict__ Ub)
{
    extern __shared__ char smraw[];
    ulonglong2* Up = (ulonglong2*)smraw;                     // [256 k][32 hcol]
    float* hraw = (float*)(smraw + UP_BYTES);                // [256 k][16 row]
    ull* red = (ull*)(smraw + UP_BYTES + HR_BYTES);          // [256 thr][19]
    const uint32_t hraw_addr = (uint32_t)__cvta_generic_to_shared(hraw);

    const int tid = threadIdx.x;
    const int gr  = blockIdx.x >> 3;              // group 0..15
    const int c   = blockIdx.x & 7;               // rank in group
    const int d   = gr >> 3;                      // direction
    const int rb  = (gr & 7) * 16;                // batch row base
    const float* U = d ? Ub : Uf;

    const int w    = tid >> 5;                    // warp -> k-slice [32w,32w+32)
    const int lane = tid & 31;
    const int rg   = lane & 1;                    // rows 8rg..8rg+7
    const int cg   = lane >> 1;                   // hcols {cg, cg+16}

    // final-tile identity (post-reduction)
    const int jf = tid & 31;                      // hcol within CTA
    const int q  = tid >> 5;                      // rows {2q, 2q+1}
    const int ghcol = c * 32 + jf;

    // Token dtype guard (jnp.int64 silently x32 in JAX unless x64 enabled).
    const bool is64 = ((tokens[1] | tokens[3] | tokens[5] | tokens[7]) == 0);
    const int ts = is64 ? 2 : 1;

    // Load U: Up[k][j] = { (u_i,u_f), (u_g,u_o) } at hcol c*32+j
    for (int i = tid; i < 8192; i += 256) {
        int k = i >> 5, j = i & 31;
        const float* ub = U + (size_t)k * G4H + c * 32 + j;
        ulonglong2 e;
        e.x = pack2(ub[0],   ub[256]);
        e.y = pack2(ub[512], ub[768]);
        Up[k * 32 + j] = e;
    }
    // zero h buffer (h(-1) = 0)
    for (int i = tid; i < 4096; i += 256) hraw[i] = 0.f;
    __syncthreads();

    const int* tr0 = tokens + (size_t)(rb + 2 * q + 0) * TT * ts;
    const int* tr1 = tokens + (size_t)(rb + 2 * q + 1) * TT * ts;
    const int* myPeerFlag = &g_flag[gr][w][0];
    int* myFlag = &g_flag[gr][c][0];

    // prefetch tokens for t = 0
    int te0 = d ? (TT - 1) : 0;
    int tk0 = tr0[te0 * ts], tk1 = tr1[te0 * ts];

    float cs0 = 0.f, cs1 = 0.f;

    // gather constants
    const int lane_src = 2 * (jf & 15) + (q >> 2);
    const int idx0 = ((2 * q) & 7) * 2 + (jf >> 4);

    // per-warp slice copy addresses (slice w = 2KB contiguous)
    const uint32_t slice_dst = hraw_addr + (uint32_t)(w * 2048) + (uint32_t)(lane * 16);

    for (int t = 0; t < TT; t++) {
        // ---- P loads for this step (consumed after reduction) ----
        int tv0 = (tk0 >= 0 && tk0 < VV) ? tk0 : 0;
        int tv1 = (tk1 >= 0 && tk1 < VV) ? tk1 : 0;
        const float* Pb0 = g_P + (size_t)tv0 * 2048 + d * 1024 + ghcol;
        const float* Pb1 = g_P + (size_t)tv1 * 2048 + d * 1024 + ghcol;
        float p00 = Pb0[0], p01 = Pb0[256], p02 = Pb0[512], p03 = Pb0[768];
        float p10 = Pb1[0], p11 = Pb1[256], p12 = Pb1[512], p13 = Pb1[768];

        // prefetch tokens for t+1
        if (t + 1 < TT) {
            int te = d ? (TT - 2 - t) : (t + 1);
            tk0 = tr0[te * ts]; tk1 = tr1[te * ts];
        }

        // ---- per-warp: acquire peer w's h(t-1) slice, copy 2KB ----
        if (t > 0) {
            while (ld_acq(myPeerFlag) < t) { }
            const char* src = (const char*)&g_hx[gr][t & 1][w * 32][0] + lane * 16;
            #pragma unroll
            for (int qq = 0; qq < 4; qq++)
                cpasync16(slice_dst + (uint32_t)(qq * 512), src + qq * 512);
            cp_commit();
            cp_wait<0>();
            __syncwarp();
        }

        // ---- k-loop over this warp's 32-k slice ----
        const ulonglong2* ub2 = Up + cg;
        ull aIF[8][2] = {}, aGO[8][2] = {};
        const int kbeg = w * 32;
        #pragma unroll 8
        for (int k = kbeg; k < kbeg + 32; k++) {
            float4 hA = *(const float4*)(hraw + k * 16 + 8 * rg);
            float4 hB = *(const float4*)(hraw + k * 16 + 8 * rg + 4);
            ulonglong2 uA = ub2[k * 32];         // hcol cg
            ulonglong2 uB = ub2[k * 32 + 16];    // hcol cg+16
            ull hd0 = pack2(hA.x, hA.x), hd1 = pack2(hA.y, hA.y);
            ull hd2 = pack2(hA.z, hA.z), hd3 = pack2(hA.w, hA.w);
            ull hd4 = pack2(hB.x, hB.x), hd5 = pack2(hB.y, hB.y);
            ull hd6 = pack2(hB.z, hB.z), hd7 = pack2(hB.w, hB.w);
            ffma2(aIF[0][0], hd0, uA.x); ffma2(aGO[0][0], hd0, uA.y);
            ffma2(aIF[0][1], hd0, uB.x); ffma2(aGO[0][1], hd0, uB.y);
            ffma2(aIF[1][0], hd1, uA.x); ffma2(aGO[1][0], hd1, uA.y);
            ffma2(aIF[1][1], hd1, uB.x); ffma2(aGO[1][1], hd1, uB.y);
            ffma2(aIF[2][0], hd2, uA.x); ffma2(aGO[2][0], hd2, uA.y);
            ffma2(aIF[2][1], hd2, uB.x); ffma2(aGO[2][1], hd2, uB.y);
            ffma2(aIF[3][0], hd3, uA.x); ffma2(aGO[3][0], hd3, uA.y);
            ffma2(aIF[3][1], hd3, uB.x); ffma2(aGO[3][1], hd3, uB.y);
            ffma2(aIF[4][0], hd4, uA.x); ffma2(aGO[4][0], hd4, uA.y);
            ffma2(aIF[4][1], hd4, uB.x); ffma2(aGO[4][1], hd4, uB.y);
            ffma2(aIF[5][0], hd5, uA.x); ffma2(aGO[5][0], hd5, uA.y);
            ffma2(aIF[5][1], hd5, uB.x); ffma2(aGO[5][1], hd5, uB.y);
            ffma2(aIF[6][0], hd6, uA.x); ffma2(aGO[6][0], hd6, uA.y);
            ffma2(aIF[6][1], hd6, uB.x); ffma2(aGO[6][1], hd6, uB.y);
            ffma2(aIF[7][0], hd7, uA.x); ffma2(aGO[7][0], hd7, uA.y);
            ffma2(aIF[7][1], hd7, uB.x); ffma2(aGO[7][1], hd7, uB.y);
        }

        ull* myred = red + tid * RED_STRIDE;

        // ---- reduction pass 1: IF ----
        #pragma unroll
        for (int i = 0; i < 8; i++) {
            myred[2 * i]     = aIF[i][0];
            myred[2 * i + 1] = aIF[i][1];
        }
        __syncthreads();
        ull zIF0 = 0ull, zIF1 = 0ull;
        #pragma unroll
        for (int w8 = 0; w8 < 8; w8++) {
            const ull* pr = red + (w8 * 32 + lane_src) * RED_STRIDE;
            addf2(zIF0, pr[idx0]);
            addf2(zIF1, pr[idx0 + 2]);
        }
        __syncthreads();

        // ---- reduction pass 2: GO ----
        #pragma unroll
        for (int i = 0; i < 8; i++) {
            myred[2 * i]     = aGO[i][0];
            myred[2 * i + 1] = aGO[i][1];
        }
        __syncthreads();
        ull zGO0 = 0ull, zGO1 = 0ull;
        #pragma unroll
        for (int w8 = 0; w8 < 8; w8++) {
            const ull* pr = red + (w8 * 32 + lane_src) * RED_STRIDE;
            addf2(zGO0, pr[idx0]);
            addf2(zGO1, pr[idx0 + 2]);
        }

        // ---- activation (rows 2q, 2q+1; hcol jf) ----
        float2 vIF0 = unpack2(zIF0), vGO0 = unpack2(zGO0);
        float2 vIF1 = unpack2(zIF1), vGO1 = unpack2(zGO1);
        float i0 = sigm(vIF0.x + p00), f0 = sigm(vIF0.y + p01);
        float g0 = tanhf(vGO0.x + p02), o0 = sigm(vGO0.y + p03);
        float i1 = sigm(vIF1.x + p10), f1 = sigm(vIF1.y + p11);
        float g1 = tanhf(vGO1.x + p12), o1 = sigm(vGO1.y + p13);
        cs0 = f0 * cs0 + i0 * g0;
        cs1 = f1 * cs1 + i1 * g1;
        float h0 = o0 * tanhf(cs0);
        float h1 = o1 * tanhf(cs1);

        if (t == TT - 1) {
            *(float2*)&g_hfinT[d][ghcol][rb + 2 * q] = make_float2(h0, h1);
        } else {
            // publish h(t) into parity slot (t+1)&1, then release flag
            *(float2*)&g_hx[gr][(t + 1) & 1][ghcol][2 * q] = make_float2(h0, h1);
            __syncthreads();                       // all CTA stores issued
            if (tid == 0) st_rel(myFlag, t + 1);   // release: publishes CTA's h
        }
    }
}

// =====================================================================
// Kernel C: head.  h1 = relu([hf|hb] @ W1 + b1); out = softmax(h1 @ W2 + b2)
// =====================================================================
__global__ void __launch_bounds__(256) head_kernel(
    const float* __restrict__ W1, const float* __restrict__ b1,
    const float* __restrict__ W2, const float* __restrict__ b2,
    float* __restrict__ out)
{
    __shared__ float hc[8][512];
    __shared__ float h1[8][256];

    const int tid = threadIdx.x;
    const int rb = blockIdx.x * 8;

    for (int i = tid; i < 4096; i += 256) {
        int rr = i >> 9, k = i & 511;
        int dd = k >> 8, kk = k & 255;
        hc[rr][k] = g_hfinT[dd][kk][rb + rr];
    }
    __syncthreads();

    const int jj = tid;
    float acc[8] = {0.f, 0.f, 0.f, 0.f, 0.f, 0.f, 0.f, 0.f};
    for (int k = 0; k < 512; k++) {
        float wv = W1[(size_t)k * HH + jj];
        #pragma unroll
        for (int rr = 0; rr < 8; rr++) acc[rr] += hc[rr][k] * wv;
    }
    float bj = b1[jj];
    #pragma unroll
    for (int rr = 0; rr < 8; rr++) h1[rr][jj] = fmaxf(acc[rr] + bj, 0.f);
    __syncthreads();

    const int rr = tid >> 5, cc = tid & 31;
    float l = b2[cc];
    for (int k = 0; k < HH; k++) l += h1[rr][k] * W2[(size_t)k * NC + cc];

    float m = l;
    #pragma unroll
    for (int o = 16; o > 0; o >>= 1) m = fmaxf(m, __shfl_xor_sync(0xffffffffu, m, o));
    float e = expf(l - m);
    float ssum = e;
    #pragma unroll
    for (int o = 16; o > 0; o >>= 1) ssum += __shfl_xor_sync(0xffffffffu, ssum, o);
    out[(size_t)(rb + rr) * NC + cc] = e / ssum;
}

// =====================================================================
extern "C" void kernel_launch(void* const* d_in, const int* in_sizes, int n_in,
                              void* d_out, int out_size)
{
    const int*   tokens = (const int*)d_in[0];
    const float* emb = (const float*)d_in[1];
    const float* Wf  = (const float*)d_in[2];
    const float* Uf  = (const float*)d_in[3];
    const float* bf  = (const float*)d_in[4];
    const float* Wb  = (const float*)d_in[5];
    const float* Ub  = (const float*)d_in[6];
    const float* bb  = (const float*)d_in[7];
    const float* W1  = (const float*)d_in[8];
    const float* b1  = (const float*)d_in[9];
    const float* W2  = (const float*)d_in[10];
    const float* b2  = (const float*)d_in[11];
    float* out = (float*)d_out;

    cudaFuncSetAttribute(lstm_kernel, cudaFuncAttributeMaxDynamicSharedMemorySize, LSTM_SMEM_BYTES);

    proj_kernel<<<dim3(32, 500), 256>>>(emb, Wf, bf, Wb, bb);
    lstm_kernel<<<128, 256, LSTM_SMEM_BYTES>>>(tokens, Uf, Ub);
    head_kernel<<<16, 256>>>(W1, b1, W2, b2, out);
}

// round 14
// speedup vs baseline: 1.0971x; 1.0456x over previous
#include <cuda_runtime.h>
#include <cstddef>
#include <cstdint>

// Problem constants
#define BB   128     // batch
#define TT   512     // seq len
#define EE   256     // embed dim
#define HH   256     // hidden
#define G4H  1024    // 4*H
#define VV   32000   // vocab
#define NC   32      // classes

typedef unsigned long long ull;

// ---------------- device scratch (no allocations allowed) ----------------
__device__ float g_P[(size_t)VV * 2048];       // [V][2*4H] vocab projection
__device__ float g_hx[16][2][HH][16];          // [group][parity][hcol][row] h exchange
__device__ float g_hfinT[2][HH][BB];           // final hidden per direction, transposed
__device__ int   g_flag[16][8][32];            // per-(group,CTA) release flags, 128B lines

// ---------------- f32x2 helpers ----------------
__device__ __forceinline__ ull pack2(float lo, float hi) {
    ull r;
    asm("mov.b64 %0, {%1, %2};" : "=l"(r) : "f"(lo), "f"(hi));
    return r;
}
__device__ __forceinline__ float2 unpack2(ull v) {
    float2 r;
    asm("mov.b64 {%0, %1}, %2;" : "=f"(r.x), "=f"(r.y) : "l"(v));
    return r;
}
__device__ __forceinline__ void ffma2(ull& d, ull a, ull b) {
    asm("fma.rn.f32x2 %0, %1, %2, %0;" : "+l"(d) : "l"(a), "l"(b));
}
__device__ __forceinline__ void addf2(ull& d, ull a) {
    asm("add.rn.f32x2 %0, %0, %1;" : "+l"(d) : "l"(a));
}

__device__ __forceinline__ int ld_acq(const int* p) {
    int v;
    asm volatile("ld.acquire.gpu.b32 %0, [%1];" : "=r"(v) : "l"(p));
    return v;
}
__device__ __forceinline__ void st_rel(int* p, int v) {
    asm volatile("st.release.gpu.b32 [%0], %1;" :: "l"(p), "r"(v) : "memory");
}

// fast activations (MUFU path; ~1e-6 abs error, contractive dynamics)
__device__ __forceinline__ float fsigm(float x) {
    return __fdividef(1.f, 1.f + __expf(-x));
}
__device__ __forceinline__ float ftanh(float x) {
    return 2.f * __fdividef(1.f, 1.f + __expf(-2.f * x)) - 1.f;
}
__device__ __forceinline__ float sigm(float x) { return 1.0f / (1.0f + expf(-x)); }

__device__ __forceinline__ void cpasync16(uint32_t dst, const void* src) {
    asm volatile("cp.async.cg.shared.global [%0], [%1], 16;" :: "r"(dst), "l"(src) : "memory");
}
__device__ __forceinline__ void cp_commit() {
    asm volatile("cp.async.commit_group;" ::: "memory");
}
template<int N> __device__ __forceinline__ void cp_wait() {
    asm volatile("cp.async.wait_group %0;" :: "n"(N) : "memory");
}

// =====================================================================
// Kernel A: P[v, d*1024+g] = sum_e emb[v,e] * W{f,b}[e,g] + b{f,b}[g]
// EXACT R11/R13 version (measured 754us). Also resets exchange flags.
// =====================================================================
__global__ void __launch_bounds__(256) proj_kernel(
    const float* __restrict__ emb,
    const float* __restrict__ Wf, const float* __restrict__ bf,
    const float* __restrict__ Wb, const float* __restrict__ bb)
{
    if (blockIdx.x == 0 && blockIdx.y == 0 && threadIdx.x < 128)
        g_flag[threadIdx.x >> 3][threadIdx.x & 7][0] = 0;

    __shared__ float As[2][64][16];   // [stage][m][k] raw A
    __shared__ float Bs[2][16][64];   // [stage][k][n] raw B

    const int tid = threadIdx.x;
    const int tx = tid & 15, ty = tid >> 4;
    const int m0 = ty * 4, n0 = tx * 4;
    const int vbase = blockIdx.y * 64;
    const int nbase = blockIdx.x * 64;
    const int d = nbase >> 10;
    const float* W    = d ? Wb : Wf;
    const float* bias = d ? bb : bf;
    const int gbase = nbase & 1023;

    const uint32_t asA = (uint32_t)__cvta_generic_to_shared(&As[0][0][0]);
    const uint32_t asB = (uint32_t)__cvta_generic_to_shared(&Bs[0][0][0]);

    const int ar = tid >> 2, aq = tid & 3;     // A: row, k-quad
    const int br = tid >> 4, bsg = tid & 15;   // B: k-row, col-quad

    ull acc[4][2] = {};

    {
        cpasync16(asA + (uint32_t)((ar * 16 + aq * 4) * 4),
                  emb + (size_t)(vbase + ar) * EE + aq * 4);
        cpasync16(asB + (uint32_t)((br * 64 + bsg * 4) * 4),
                  W + (size_t)br * G4H + gbase + bsg * 4);
        cp_commit();
    }

    for (int s = 0; s < 16; s++) {
        if (s + 1 < 16) {
            int b = (s + 1) & 1;
            cpasync16(asA + (uint32_t)(b * 4096 + (ar * 16 + aq * 4) * 4),
                      emb + (size_t)(vbase + ar) * EE + (s + 1) * 16 + aq * 4);
            cpasync16(asB + (uint32_t)(b * 4096 + (br * 64 + bsg * 4) * 4),
                      W + (size_t)((s + 1) * 16 + br) * G4H + gbase + bsg * 4);
            cp_commit();
            cp_wait<1>();
        } else {
            cp_wait<0>();
        }
        __syncthreads();

        const int b = s & 1;
        #pragma unroll
        for (int k = 0; k < 16; k++) {
            float a0 = As[b][m0 + 0][k];
            float a1 = As[b][m0 + 1][k];
            float a2 = As[b][m0 + 2][k];
            float a3 = As[b][m0 + 3][k];
            ulonglong2 bb2 = *(const ulonglong2*)&Bs[b][k][n0];
            ull ad0 = pack2(a0, a0), ad1 = pack2(a1, a1);
            ull ad2 = pack2(a2, a2), ad3 = pack2(a3, a3);
            ffma2(acc[0][0], ad0, bb2.x); ffma2(acc[0][1], ad0, bb2.y);
            ffma2(acc[1][0], ad1, bb2.x); ffma2(acc[1][1], ad1, bb2.y);
            ffma2(acc[2][0], ad2, bb2.x); ffma2(acc[2][1], ad2, bb2.y);
            ffma2(acc[3][0], ad3, bb2.x); ffma2(acc[3][1], ad3, bb2.y);
        }
        __syncthreads();
    }

    #pragma unroll
    for (int i = 0; i < 4; i++) {
        int v = vbase + m0 + i;
        #pragma unroll
        for (int p = 0; p < 2; p++) {
            float2 va = unpack2(acc[i][p]);
            int cc = n0 + 2 * p;
            va.x += bias[gbase + cc];
            va.y += bias[gbase + cc + 1];
            *(float2*)&g_P[(size_t)v * 2048 + nbase + cc] = va;
        }
    }
}

// =====================================================================
// Kernel B: register-tiled 8-way-k-split LSTM, per-warp flag exchange.
// R13 core + this round:
//  - merged single-pass reduction (IF+GO together): 4 syncs/step -> 2
//  - fast MUFU activations
//  - own-slice shortcut: warp w==c reads its slice from local STS, no poll
// =====================================================================
#define UP_BYTES   131072                     // [256 k][32 hcol] ulonglong2
#define HR_BYTES   16384                      // [256 k][16 row] float, single buf
#define RED_STRIDE 33                         // ull per thread row (32 + pad)
#define RED_BYTES  (256 * RED_STRIDE * 8)     // 67584
#define LSTM_SMEM_BYTES (UP_BYTES + HR_BYTES + RED_BYTES)   // 215040

__global__ void __launch_bounds__(256) lstm_kernel(
    const int* __restrict__ tokens,
    const float* __restrict__ Uf, const float* __restrict__ Ub)
{
    extern __shared__ char smraw[];
    ulonglong2* Up = (ulonglong2*)smraw;                     // [256 k][32 hcol]
    float* hraw = (float*)(smraw + UP_BYTES);                // [256 k][16 row]
    ull* red = (ull*)(smraw + UP_BYTES + HR_BYTES);          // [256 thr][33]
    const uint32_t hraw_addr = (uint32_t)__cvta_generic_to_shared(hraw);

    const int tid = threadIdx.x;
    const int gr  = blockIdx.x >> 3;              // group 0..15
    const int c   = blockIdx.x & 7;               // rank in group
    const int d   = gr >> 3;                      // direction
    const int rb  = (gr & 7) * 16;                // batch row base
    const float* U = d ? Ub : Uf;

    const int w    = tid >> 5;                    // warp -> k-slice [32w,32w+32)
    const int lane = tid & 31;
    const int rg   = lane & 1;                    // rows 8rg..8rg+7
    const int cg   = lane >> 1;                   // hcols {cg, cg+16}

    // final-tile identity (post-reduction)
    const int jf = tid & 31;                      // hcol within CTA
    const int q  = tid >> 5;                      // rows {2q, 2q+1}
    const int ghcol = c * 32 + jf;

    // Token dtype guard (jnp.int64 silently x32 in JAX unless x64 enabled).
    const bool is64 = ((tokens[1] | tokens[3] | tokens[5] | tokens[7]) == 0);
    const int ts = is64 ? 2 : 1;

    // Load U: Up[k][j] = { (u_i,u_f), (u_g,u_o) } at hcol c*32+j
    for (int i = tid; i < 8192; i += 256) {
        int k = i >> 5, j = i & 31;
        const float* ub = U + (size_t)k * G4H + c * 32 + j;
        ulonglong2 e;
        e.x = pack2(ub[0],   ub[256]);
        e.y = pack2(ub[512], ub[768]);
        Up[k * 32 + j] = e;
    }
    // zero h buffer (h(-1) = 0)
    for (int i = tid; i < 4096; i += 256) hraw[i] = 0.f;
    __syncthreads();

    const int* tr0 = tokens + (size_t)(rb + 2 * q + 0) * TT * ts;
    const int* tr1 = tokens + (size_t)(rb + 2 * q + 1) * TT * ts;
    const int* myPeerFlag = &g_flag[gr][w][0];
    int* myFlag = &g_flag[gr][c][0];

    // prefetch tokens for t = 0
    int te0 = d ? (TT - 1) : 0;
    int tk0 = tr0[te0 * ts], tk1 = tr1[te0 * ts];

    float cs0 = 0.f, cs1 = 0.f;

    // gather constants
    const int lane_src = 2 * (jf & 15) + (q >> 2);
    const int idx0 = ((2 * q) & 7) * 2 + (jf >> 4);

    // per-warp slice copy addresses (slice w = 2KB contiguous)
    const uint32_t slice_dst = hraw_addr + (uint32_t)(w * 2048) + (uint32_t)(lane * 16);
    const bool own_slice = (w == c);

    for (int t = 0; t < TT; t++) {
        // ---- P loads for this step (consumed after reduction) ----
        int tv0 = (tk0 >= 0 && tk0 < VV) ? tk0 : 0;
        int tv1 = (tk1 >= 0 && tk1 < VV) ? tk1 : 0;
        const float* Pb0 = g_P + (size_t)tv0 * 2048 + d * 1024 + ghcol;
        const float* Pb1 = g_P + (size_t)tv1 * 2048 + d * 1024 + ghcol;
        float p00 = Pb0[0], p01 = Pb0[256], p02 = Pb0[512], p03 = Pb0[768];
        float p10 = Pb1[0], p11 = Pb1[256], p12 = Pb1[512], p13 = Pb1[768];

        // prefetch tokens for t+1
        if (t + 1 < TT) {
            int te = d ? (TT - 2 - t) : (t + 1);
            tk0 = tr0[te * ts]; tk1 = tr1[te * ts];
        }

        // ---- per-warp: acquire peer w's h(t-1) slice (own slice is local) ----
        if (t > 0 && !own_slice) {
            while (ld_acq(myPeerFlag) < t) { }
            const char* src = (const char*)&g_hx[gr][t & 1][w * 32][0] + lane * 16;
            #pragma unroll
            for (int qq = 0; qq < 4; qq++)
                cpasync16(slice_dst + (uint32_t)(qq * 512), src + qq * 512);
            cp_commit();
            cp_wait<0>();
            __syncwarp();
        }

        // ---- k-loop over this warp's 32-k slice ----
        const ulonglong2* ub2 = Up + cg;
        ull aIF[8][2] = {}, aGO[8][2] = {};
        const int kbeg = w * 32;
        #pragma unroll 8
        for (int k = kbeg; k < kbeg + 32; k++) {
            float4 hA = *(const float4*)(hraw + k * 16 + 8 * rg);
            float4 hB = *(const float4*)(hraw + k * 16 + 8 * rg + 4);
            ulonglong2 uA = ub2[k * 32];         // hcol cg
            ulonglong2 uB = ub2[k * 32 + 16];    // hcol cg+16
            ull hd0 = pack2(hA.x, hA.x), hd1 = pack2(hA.y, hA.y);
            ull hd2 = pack2(hA.z, hA.z), hd3 = pack2(hA.w, hA.w);
            ull hd4 = pack2(hB.x, hB.x), hd5 = pack2(hB.y, hB.y);
            ull hd6 = pack2(hB.z, hB.z), hd7 = pack2(hB.w, hB.w);
            ffma2(aIF[0][0], hd0, uA.x); ffma2(aGO[0][0], hd0, uA.y);
            ffma2(aIF[0][1], hd0, uB.x); ffma2(aGO[0][1], hd0, uB.y);
            ffma2(aIF[1][0], hd1, uA.x); ffma2(aGO[1][0], hd1, uA.y);
            ffma2(aIF[1][1], hd1, uB.x); ffma2(aGO[1][1], hd1, uB.y);
            ffma2(aIF[2][0], hd2, uA.x); ffma2(aGO[2][0], hd2, uA.y);
            ffma2(aIF[2][1], hd2, uB.x); ffma2(aGO[2][1], hd2, uB.y);
            ffma2(aIF[3][0], hd3, uA.x); ffma2(aGO[3][0], hd3, uA.y);
            ffma2(aIF[3][1], hd3, uB.x); ffma2(aGO[3][1], hd3, uB.y);
            ffma2(aIF[4][0], hd4, uA.x); ffma2(aGO[4][0], hd4, uA.y);
            ffma2(aIF[4][1], hd4, uB.x); ffma2(aGO[4][1], hd4, uB.y);
            ffma2(aIF[5][0], hd5, uA.x); ffma2(aGO[5][0], hd5, uA.y);
            ffma2(aIF[5][1], hd5, uB.x); ffma2(aGO[5][1], hd5, uB.y);
            ffma2(aIF[6][0], hd6, uA.x); ffma2(aGO[6][0], hd6, uA.y);
            ffma2(aIF[6][1], hd6, uB.x); ffma2(aGO[6][1], hd6, uB.y);
            ffma2(aIF[7][0], hd7, uA.x); ffma2(aGO[7][0], hd7, uA.y);
            ffma2(aIF[7][1], hd7, uB.x); ffma2(aGO[7][1], hd7, uB.y);
        }

        // ---- merged reduction: store IF+GO partials, one sync, one gather ----
        ull* myred = red + tid * RED_STRIDE;
        #pragma unroll
        for (int i = 0; i < 8; i++) {
            myred[2 * i]          = aIF[i][0];
            myred[2 * i + 1]      = aIF[i][1];
            myred[16 + 2 * i]     = aGO[i][0];
            myred[16 + 2 * i + 1] = aGO[i][1];
        }
        __syncthreads();
        ull zIF0 = 0ull, zIF1 = 0ull, zGO0 = 0ull, zGO1 = 0ull;
        #pragma unroll
        for (int w8 = 0; w8 < 8; w8++) {
            const ull* pr = red + (w8 * 32 + lane_src) * RED_STRIDE;
            addf2(zIF0, pr[idx0]);
            addf2(zIF1, pr[idx0 + 2]);
            addf2(zGO0, pr[16 + idx0]);
            addf2(zGO1, pr[16 + idx0 + 2]);
        }

        // ---- activation (rows 2q, 2q+1; hcol jf) ----
        float2 vIF0 = unpack2(zIF0), vGO0 = unpack2(zGO0);
        float2 vIF1 = unpack2(zIF1), vGO1 = unpack2(zGO1);
        float i0 = fsigm(vIF0.x + p00), f0 = fsigm(vIF0.y + p01);
        float g0 = ftanh(vGO0.x + p02), o0 = fsigm(vGO0.y + p03);
        float i1 = fsigm(vIF1.x + p10), f1 = fsigm(vIF1.y + p11);
        float g1 = ftanh(vGO1.x + p12), o1 = fsigm(vGO1.y + p13);
        cs0 = f0 * cs0 + i0 * g0;
        cs1 = f1 * cs1 + i1 * g1;
        float h0 = o0 * ftanh(cs0);
        float h1 = o1 * ftanh(cs1);

        if (t == TT - 1) {
            *(float2*)&g_hfinT[d][ghcol][rb + 2 * q] = make_float2(h0, h1);
        } else {
            // publish h(t): global for peers + local STS for own warp c's slice
            *(float2*)&g_hx[gr][(t + 1) & 1][ghcol][2 * q] = make_float2(h0, h1);
            *(float2*)&hraw[(c * 32 + jf) * 16 + 2 * q] = make_float2(h0, h1);
            __syncthreads();                       // all CTA stores issued; red reusable
            if (tid == 0) st_rel(myFlag, t + 1);   // release: publishes CTA's h
        }
    }
}

// =====================================================================
// Kernel C: head.  h1 = relu([hf|hb] @ W1 + b1); out = softmax(h1 @ W2 + b2)
// =====================================================================
__global__ void __launch_bounds__(256) head_kernel(
    const float* __restrict__ W1, const float* __restrict__ b1,
    const float* __restrict__ W2, const float* __restrict__ b2,
    float* __restrict__ out)
{
    __shared__ float hc[8][512];
    __shared__ float h1[8][256];

    const int tid = threadIdx.x;
    const int rb = blockIdx.x * 8;

    for (int i = tid; i < 4096; i += 256) {
        int rr = i >> 9, k = i & 511;
        int dd = k >> 8, kk = k & 255;
        hc[rr][k] = g_hfinT[dd][kk][rb + rr];
    }
    __syncthreads();

    const int jj = tid;
    float acc[8] = {0.f, 0.f, 0.f, 0.f, 0.f, 0.f, 0.f, 0.f};
    for (int k = 0; k < 512; k++) {
        float wv = W1[(size_t)k * HH + jj];
        #pragma unroll
        for (int rr = 0; rr < 8; rr++) acc[rr] += hc[rr][k] * wv;
    }
    float bj = b1[jj];
    #pragma unroll
    for (int rr = 0; rr < 8; rr++) h1[rr][jj] = fmaxf(acc[rr] + bj, 0.f);
    __syncthreads();

    const int rr = tid >> 5, cc = tid & 31;
    float l = b2[cc];
    for (int k = 0; k < HH; k++) l += h1[rr][k] * W2[(size_t)k * NC + cc];

    float m = l;
    #pragma unroll
    for (int o = 16; o > 0; o >>= 1) m = fmaxf(m, __shfl_xor_sync(0xffffffffu, m, o));
    float e = expf(l - m);
    float ssum = e;
    #pragma unroll
    for (int o = 16; o > 0; o >>= 1) ssum += __shfl_xor_sync(0xffffffffu, ssum, o);
    out[(size_t)(rb + rr) * NC + cc] = e / ssum;
}

// =====================================================================
extern "C" void kernel_launch(void* const* d_in, const int* in_sizes, int n_in,
                              void* d_out, int out_size)
{
    const int*   tokens = (const int*)d_in[0];
    const float* emb = (const float*)d_in[1];
    const float* Wf  = (const float*)d_in[2];
    const float* Uf  = (const float*)d_in[3];
    const float* bf  = (const float*)d_in[4];
    const float* Wb  = (const float*)d_in[5];
    const float* Ub  = (const float*)d_in[6];
    const float* bb  = (const float*)d_in[7];
    const float* W1  = (const float*)d_in[8];
    const float* b1  = (const float*)d_in[9];
    const float* W2  = (const float*)d_in[10];
    const float* b2  = (const float*)d_in[11];
    float* out = (float*)d_out;

    cudaFuncSetAttribute(lstm_kernel, cudaFuncAttributeMaxDynamicSharedMemorySize, LSTM_SMEM_BYTES);

    proj_kernel<<<dim3(32, 500), 256>>>(emb, Wf, bf, Wb, bb);
    lstm_kernel<<<128, 256, LSTM_SMEM_BYTES>>>(tokens, Uf, Ub);
    head_kernel<<<16, 256>>>(W1, b1, W2, b2, out);
}

// round 15
// speedup vs baseline: 1.1415x; 1.0404x over previous
#include <cuda_runtime.h>
#include <cstddef>
#include <cstdint>

// Problem constants
#define BB   128     // batch
#define TT   512     // seq len
#define EE   256     // embed dim
#define HH   256     // hidden
#define G4H  1024    // 4*H
#define VV   32000   // vocab
#define NC   32      // classes

typedef unsigned long long ull;

// ---------------- device scratch (no allocations allowed) ----------------
__device__ float g_P[(size_t)VV * 2048];       // [V][2*4H] vocab projection
__device__ float g_hx[16][2][HH][16];          // [group][parity][hcol][row] h exchange
__device__ float g_hfinT[2][HH][BB];           // final hidden per direction, transposed
__device__ int   g_flag[16][8][32];            // per-(group,CTA) release flags, 128B lines

// ---------------- f32x2 helpers ----------------
__device__ __forceinline__ ull pack2(float lo, float hi) {
    ull r;
    asm("mov.b64 %0, {%1, %2};" : "=l"(r) : "f"(lo), "f"(hi));
    return r;
}
__device__ __forceinline__ float2 unpack2(ull v) {
    float2 r;
    asm("mov.b64 {%0, %1}, %2;" : "=f"(r.x), "=f"(r.y) : "l"(v));
    return r;
}
__device__ __forceinline__ void ffma2(ull& d, ull a, ull b) {
    asm("fma.rn.f32x2 %0, %1, %2, %0;" : "+l"(d) : "l"(a), "l"(b));
}
__device__ __forceinline__ void addf2(ull& d, ull a) {
    asm("add.rn.f32x2 %0, %0, %1;" : "+l"(d) : "l"(a));
}

__device__ __forceinline__ int ld_acq(const int* p) {
    int v;
    asm volatile("ld.acquire.gpu.b32 %0, [%1];" : "=r"(v) : "l"(p));
    return v;
}
__device__ __forceinline__ void st_rel(int* p, int v) {
    asm volatile("st.release.gpu.b32 [%0], %1;" :: "l"(p), "r"(v) : "memory");
}

// fast activations (MUFU path; ~1e-6 abs error, contractive dynamics)
__device__ __forceinline__ float fsigm(float x) {
    return __fdividef(1.f, 1.f + __expf(-x));
}
__device__ __forceinline__ float ftanh(float x) {
    return 2.f * __fdividef(1.f, 1.f + __expf(-2.f * x)) - 1.f;
}

__device__ __forceinline__ void cpasync16(uint32_t dst, const void* src) {
    asm volatile("cp.async.cg.shared.global [%0], [%1], 16;" :: "r"(dst), "l"(src) : "memory");
}
__device__ __forceinline__ void cp_commit() {
    asm volatile("cp.async.commit_group;" ::: "memory");
}
template<int N> __device__ __forceinline__ void cp_wait() {
    asm volatile("cp.async.wait_group %0;" :: "n"(N) : "memory");
}

// =====================================================================
// Kernel A: P[v, d*1024+g] = sum_e emb[v,e] * W{f,b}[e,g] + b{f,b}[g]
// CTA tile 32(m) x 128(n), 128 threads, thread tile 4m x 8n (two 4-col
// groups at n0 and n0+64). Per k: 4 LDS.32 + 2 LDS.128 + 4 movs +
// 16 FFMA2 = 26 instr per 32-cyc FMA budget -> FMA-bound.
// 2-stage cp.async double buffer. Also resets exchange flags.
// =====================================================================
__global__ void __launch_bounds__(128) proj_kernel(
    const float* __restrict__ emb,
    const float* __restrict__ Wf, const float* __restrict__ bf,
    const float* __restrict__ Wb, const float* __restrict__ bb)
{
    if (blockIdx.x == 0 && blockIdx.y == 0 && threadIdx.x < 128)
        g_flag[threadIdx.x >> 3][threadIdx.x & 7][0] = 0;

    __shared__ float As[2][32][16];    // [stage][m][k]
    __shared__ float Bs[2][16][128];   // [stage][k][n]

    const int tid = threadIdx.x;
    const int tx = tid & 15, ty = tid >> 4;      // tx 0..15, ty 0..7
    const int m0 = ty * 4, n0 = tx * 4;
    const int vbase = blockIdx.y * 32;
    const int nbase = blockIdx.x * 128;
    const int d = nbase >> 10;
    const float* W    = d ? Wb : Wf;
    const float* bias = d ? bb : bf;
    const int gbase = nbase & 1023;

    const uint32_t asA = (uint32_t)__cvta_generic_to_shared(&As[0][0][0]);
    const uint32_t asB = (uint32_t)__cvta_generic_to_shared(&Bs[0][0][0]);

    // copy coords: A = 128 float4 chunks, B = 512 (4 per thread)
    const int ar = tid >> 2, aq = tid & 3;       // A: row 0..31, k-quad

    ull acc[4][4] = {};

    // issue stage 0
    cpasync16(asA + (uint32_t)((ar * 16 + aq * 4) * 4),
              emb + (size_t)(vbase + ar) * EE + aq * 4);
    #pragma unroll
    for (int j = 0; j < 4; j++) {
        int idx = tid + j * 128;
        int bk = idx >> 5, bq = idx & 31;
        cpasync16(asB + (uint32_t)((bk * 128 + bq * 4) * 4),
                  W + (size_t)bk * G4H + gbase + bq * 4);
    }
    cp_commit();

    for (int s = 0; s < 16; s++) {
        if (s + 1 < 16) {
            const int b = (s + 1) & 1;
            cpasync16(asA + (uint32_t)(b * 2048) + (uint32_t)((ar * 16 + aq * 4) * 4),
                      emb + (size_t)(vbase + ar) * EE + (s + 1) * 16 + aq * 4);
            #pragma unroll
            for (int j = 0; j < 4; j++) {
                int idx = tid + j * 128;
                int bk = idx >> 5, bq = idx & 31;
                cpasync16(asB + (uint32_t)(b * 8192) + (uint32_t)((bk * 128 + bq * 4) * 4),
                          W + (size_t)((s + 1) * 16 + bk) * G4H + gbase + bq * 4);
            }
            cp_commit();
            cp_wait<1>();
        } else {
            cp_wait<0>();
        }
        __syncthreads();

        const int b = s & 1;
        #pragma unroll
        for (int k = 0; k < 16; k++) {
            float a0 = As[b][m0 + 0][k];
            float a1 = As[b][m0 + 1][k];
            float a2 = As[b][m0 + 2][k];
            float a3 = As[b][m0 + 3][k];
            ulonglong2 bb1 = *(const ulonglong2*)&Bs[b][k][n0];
            ulonglong2 bb2 = *(const ulonglong2*)&Bs[b][k][64 + n0];
            ull ad0 = pack2(a0, a0), ad1 = pack2(a1, a1);
            ull ad2 = pack2(a2, a2), ad3 = pack2(a3, a3);
            ffma2(acc[0][0], ad0, bb1.x); ffma2(acc[0][1], ad0, bb1.y);
            ffma2(acc[0][2], ad0, bb2.x); ffma2(acc[0][3], ad0, bb2.y);
            ffma2(acc[1][0], ad1, bb1.x); ffma2(acc[1][1], ad1, bb1.y);
            ffma2(acc[1][2], ad1, bb2.x); ffma2(acc[1][3], ad1, bb2.y);
            ffma2(acc[2][0], ad2, bb1.x); ffma2(acc[2][1], ad2, bb1.y);
            ffma2(acc[2][2], ad2, bb2.x); ffma2(acc[2][3], ad2, bb2.y);
            ffma2(acc[3][0], ad3, bb1.x); ffma2(acc[3][1], ad3, bb1.y);
            ffma2(acc[3][2], ad3, bb2.x); ffma2(acc[3][3], ad3, bb2.y);
        }
        __syncthreads();
    }

    #pragma unroll
    for (int i = 0; i < 4; i++) {
        int v = vbase + m0 + i;
        #pragma unroll
        for (int p = 0; p < 4; p++) {
            float2 va = unpack2(acc[i][p]);
            int cc = (p < 2 ? n0 + 2 * p : 64 + n0 + 2 * (p - 2));
            va.x += bias[gbase + cc];
            va.y += bias[gbase + cc + 1];
            *(float2*)&g_P[(size_t)v * 2048 + nbase + cc] = va;
        }
    }
}

// =====================================================================
// Kernel B: register-tiled 8-way-k-split LSTM, per-warp flag exchange.
// BYTE-IDENTICAL to the measured R14 best (2.45ms).
// =====================================================================
#define UP_BYTES   131072                     // [256 k][32 hcol] ulonglong2
#define HR_BYTES   16384                      // [256 k][16 row] float, single buf
#define RED_STRIDE 33                         // ull per thread row (32 + pad)
#define RED_BYTES  (256 * RED_STRIDE * 8)     // 67584
#define LSTM_SMEM_BYTES (UP_BYTES + HR_BYTES + RED_BYTES)   // 215040

__global__ void __launch_bounds__(256) lstm_kernel(
    const int* __restrict__ tokens,
    const float* __restrict__ Uf, const float* __restrict__ Ub)
{
    extern __shared__ char smraw[];
    ulonglong2* Up = (ulonglong2*)smraw;                     // [256 k][32 hcol]
    float* hraw = (float*)(smraw + UP_BYTES);                // [256 k][16 row]
    ull* red = (ull*)(smraw + UP_BYTES + HR_BYTES);          // [256 thr][33]
    const uint32_t hraw_addr = (uint32_t)__cvta_generic_to_shared(hraw);

    const int tid = threadIdx.x;
    const int gr  = blockIdx.x >> 3;              // group 0..15
    const int c   = blockIdx.x & 7;               // rank in group
    const int d   = gr >> 3;                      // direction
    const int rb  = (gr & 7) * 16;                // batch row base
    const float* U = d ? Ub : Uf;

    const int w    = tid >> 5;                    // warp -> k-slice [32w,32w+32)
    const int lane = tid & 31;
    const int rg   = lane & 1;                    // rows 8rg..8rg+7
    const int cg   = lane >> 1;                   // hcols {cg, cg+16}

    const int jf = tid & 31;                      // hcol within CTA
    const int q  = tid >> 5;                      // rows {2q, 2q+1}
    const int ghcol = c * 32 + jf;

    // Token dtype guard (jnp.int64 silently x32 in JAX unless x64 enabled).
    const bool is64 = ((tokens[1] | tokens[3] | tokens[5] | tokens[7]) == 0);
    const int ts = is64 ? 2 : 1;

    // Load U: Up[k][j] = { (u_i,u_f), (u_g,u_o) } at hcol c*32+j
    for (int i = tid; i < 8192; i += 256) {
        int k = i >> 5, j = i & 31;
        const float* ub = U + (size_t)k * G4H + c * 32 + j;
        ulonglong2 e;
        e.x = pack2(ub[0],   ub[256]);
        e.y = pack2(ub[512], ub[768]);
        Up[k * 32 + j] = e;
    }
    // zero h buffer (h(-1) = 0)
    for (int i = tid; i < 4096; i += 256) hraw[i] = 0.f;
    __syncthreads();

    const int* tr0 = tokens + (size_t)(rb + 2 * q + 0) * TT * ts;
    const int* tr1 = tokens + (size_t)(rb + 2 * q + 1) * TT * ts;
    const int* myPeerFlag = &g_flag[gr][w][0];
    int* myFlag = &g_flag[gr][c][0];

    // prefetch tokens for t = 0
    int te0 = d ? (TT - 1) : 0;
    int tk0 = tr0[te0 * ts], tk1 = tr1[te0 * ts];

    float cs0 = 0.f, cs1 = 0.f;

    // gather constants
    const int lane_src = 2 * (jf & 15) + (q >> 2);
    const int idx0 = ((2 * q) & 7) * 2 + (jf >> 4);

    // per-warp slice copy addresses (slice w = 2KB contiguous)
    const uint32_t slice_dst = hraw_addr + (uint32_t)(w * 2048) + (uint32_t)(lane * 16);
    const bool own_slice = (w == c);

    for (int t = 0; t < TT; t++) {
        // ---- P loads for this step (consumed after reduction) ----
        int tv0 = (tk0 >= 0 && tk0 < VV) ? tk0 : 0;
        int tv1 = (tk1 >= 0 && tk1 < VV) ? tk1 : 0;
        const float* Pb0 = g_P + (size_t)tv0 * 2048 + d * 1024 + ghcol;
        const float* Pb1 = g_P + (size_t)tv1 * 2048 + d * 1024 + ghcol;
        float p00 = Pb0[0], p01 = Pb0[256], p02 = Pb0[512], p03 = Pb0[768];
        float p10 = Pb1[0], p11 = Pb1[256], p12 = Pb1[512], p13 = Pb1[768];

        // prefetch tokens for t+1
        if (t + 1 < TT) {
            int te = d ? (TT - 2 - t) : (t + 1);
            tk0 = tr0[te * ts]; tk1 = tr1[te * ts];
        }

        // ---- per-warp: acquire peer w's h(t-1) slice (own slice is local) ----
        if (t > 0 && !own_slice) {
            while (ld_acq(myPeerFlag) < t) { }
            const char* src = (const char*)&g_hx[gr][t & 1][w * 32][0] + lane * 16;
            #pragma unroll
            for (int qq = 0; qq < 4; qq++)
                cpasync16(slice_dst + (uint32_t)(qq * 512), src + qq * 512);
            cp_commit();
            cp_wait<0>();
            __syncwarp();
        }

        // ---- k-loop over this warp's 32-k slice ----
        const ulonglong2* ub2 = Up + cg;
        ull aIF[8][2] = {}, aGO[8][2] = {};
        const int kbeg = w * 32;
        #pragma unroll 8
        for (int k = kbeg; k < kbeg + 32; k++) {
            float4 hA = *(const float4*)(hraw + k * 16 + 8 * rg);
            float4 hB = *(const float4*)(hraw + k * 16 + 8 * rg + 4);
            ulonglong2 uA = ub2[k * 32];         // hcol cg
            ulonglong2 uB = ub2[k * 32 + 16];    // hcol cg+16
            ull hd0 = pack2(hA.x, hA.x), hd1 = pack2(hA.y, hA.y);
            ull hd2 = pack2(hA.z, hA.z), hd3 = pack2(hA.w, hA.w);
            ull hd4 = pack2(hB.x, hB.x), hd5 = pack2(hB.y, hB.y);
            ull hd6 = pack2(hB.z, hB.z), hd7 = pack2(hB.w, hB.w);
            ffma2(aIF[0][0], hd0, uA.x); ffma2(aGO[0][0], hd0, uA.y);
            ffma2(aIF[0][1], hd0, uB.x); ffma2(aGO[0][1], hd0, uB.y);
            ffma2(aIF[1][0], hd1, uA.x); ffma2(aGO[1][0], hd1, uA.y);
            ffma2(aIF[1][1], hd1, uB.x); ffma2(aGO[1][1], hd1, uB.y);
            ffma2(aIF[2][0], hd2, uA.x); ffma2(aGO[2][0], hd2, uA.y);
            ffma2(aIF[2][1], hd2, uB.x); ffma2(aGO[2][1], hd2, uB.y);
            ffma2(aIF[3][0], hd3, uA.x); ffma2(aGO[3][0], hd3, uA.y);
            ffma2(aIF[3][1], hd3, uB.x); ffma2(aGO[3][1], hd3, uB.y);
            ffma2(aIF[4][0], hd4, uA.x); ffma2(aGO[4][0], hd4, uA.y);
            ffma2(aIF[4][1], hd4, uB.x); ffma2(aGO[4][1], hd4, uB.y);
            ffma2(aIF[5][0], hd5, uA.x); ffma2(aGO[5][0], hd5, uA.y);
            ffma2(aIF[5][1], hd5, uB.x); ffma2(aGO[5][1], hd5, uB.y);
            ffma2(aIF[6][0], hd6, uA.x); ffma2(aGO[6][0], hd6, uA.y);
            ffma2(aIF[6][1], hd6, uB.x); ffma2(aGO[6][1], hd6, uB.y);
            ffma2(aIF[7][0], hd7, uA.x); ffma2(aGO[7][0], hd7, uA.y);
            ffma2(aIF[7][1], hd7, uB.x); ffma2(aGO[7][1], hd7, uB.y);
        }

        // ---- merged reduction: store IF+GO partials, one sync, one gather ----
        ull* myred = red + tid * RED_STRIDE;
        #pragma unroll
        for (int i = 0; i < 8; i++) {
            myred[2 * i]          = aIF[i][0];
            myred[2 * i + 1]      = aIF[i][1];
            myred[16 + 2 * i]     = aGO[i][0];
            myred[16 + 2 * i + 1] = aGO[i][1];
        }
        __syncthreads();
        ull zIF0 = 0ull, zIF1 = 0ull, zGO0 = 0ull, zGO1 = 0ull;
        #pragma unroll
        for (int w8 = 0; w8 < 8; w8++) {
            const ull* pr = red + (w8 * 32 + lane_src) * RED_STRIDE;
            addf2(zIF0, pr[idx0]);
            addf2(zIF1, pr[idx0 + 2]);
            addf2(zGO0, pr[16 + idx0]);
            addf2(zGO1, pr[16 + idx0 + 2]);
        }

        // ---- activation (rows 2q, 2q+1; hcol jf) ----
        float2 vIF0 = unpack2(zIF0), vGO0 = unpack2(zGO0);
        float2 vIF1 = unpack2(zIF1), vGO1 = unpack2(zGO1);
        float i0 = fsigm(vIF0.x + p00), f0 = fsigm(vIF0.y + p01);
        float g0 = ftanh(vGO0.x + p02), o0 = fsigm(vGO0.y + p03);
        float i1 = fsigm(vIF1.x + p10), f1 = fsigm(vIF1.y + p11);
        float g1 = ftanh(vGO1.x + p12), o1 = fsigm(vGO1.y + p13);
        cs0 = f0 * cs0 + i0 * g0;
        cs1 = f1 * cs1 + i1 * g1;
        float h0 = o0 * ftanh(cs0);
        float h1 = o1 * ftanh(cs1);

        if (t == TT - 1) {
            *(float2*)&g_hfinT[d][ghcol][rb + 2 * q] = make_float2(h0, h1);
        } else {
            // publish h(t): global for peers + local STS for own warp c's slice
            *(float2*)&g_hx[gr][(t + 1) & 1][ghcol][2 * q] = make_float2(h0, h1);
            *(float2*)&hraw[(c * 32 + jf) * 16 + 2 * q] = make_float2(h0, h1);
            __syncthreads();                       // all CTA stores issued; red reusable
            if (tid == 0) st_rel(myFlag, t + 1);   // release: publishes CTA's h
        }
    }
}

// =====================================================================
// Kernel C: head.  h1 = relu([hf|hb] @ W1 + b1); out = softmax(h1 @ W2 + b2)
// =====================================================================
__global__ void __launch_bounds__(256) head_kernel(
    const float* __restrict__ W1, const float* __restrict__ b1,
    const float* __restrict__ W2, const float* __restrict__ b2,
    float* __restrict__ out)
{
    __shared__ float hc[8][512];
    __shared__ float h1[8][256];

    const int tid = threadIdx.x;
    const int rb = blockIdx.x * 8;

    for (int i = tid; i < 4096; i += 256) {
        int rr = i >> 9, k = i & 511;
        int dd = k >> 8, kk = k & 255;
        hc[rr][k] = g_hfinT[dd][kk][rb + rr];
    }
    __syncthreads();

    const int jj = tid;
    float acc[8] = {0.f, 0.f, 0.f, 0.f, 0.f, 0.f, 0.f, 0.f};
    for (int k = 0; k < 512; k++) {
        float wv = W1[(size_t)k * HH + jj];
        #pragma unroll
        for (int rr = 0; rr < 8; rr++) acc[rr] += hc[rr][k] * wv;
    }
    float bj = b1[jj];
    #pragma unroll
    for (int rr = 0; rr < 8; rr++) h1[rr][jj] = fmaxf(acc[rr] + bj, 0.f);
    __syncthreads();

    const int rr = tid >> 5, cc = tid & 31;
    float l = b2[cc];
    for (int k = 0; k < HH; k++) l += h1[rr][k] * W2[(size_t)k * NC + cc];

    float m = l;
    #pragma unroll
    for (int o = 16; o > 0; o >>= 1) m = fmaxf(m, __shfl_xor_sync(0xffffffffu, m, o));
    float e = expf(l - m);
    float ssum = e;
    #pragma unroll
    for (int o = 16; o > 0; o >>= 1) ssum += __shfl_xor_sync(0xffffffffu, ssum, o);
    out[(size_t)(rb + rr) * NC + cc] = e / ssum;
}

// =====================================================================
extern "C" void kernel_launch(void* const* d_in, const int* in_sizes, int n_in,
                              void* d_out, int out_size)
{
    const int*   tokens = (const int*)d_in[0];
    const float* emb = (const float*)d_in[1];
    const float* Wf  = (const float*)d_in[2];
    const float* Uf  = (const float*)d_in[3];
    const float* bf  = (const float*)d_in[4];
    const float* Wb  = (const float*)d_in[5];
    const float* Ub  = (const float*)d_in[6];
    const float* bb  = (const float*)d_in[7];
    const float* W1  = (const float*)d_in[8];
    const float* b1  = (const float*)d_in[9];
    const float* W2  = (const float*)d_in[10];
    const float* b2  = (const float*)d_in[11];
    float* out = (float*)d_out;

    cudaFuncSetAttribute(lstm_kernel, cudaFuncAttributeMaxDynamicSharedMemorySize, LSTM_SMEM_BYTES);

    proj_kernel<<<dim3(16, 1000), 128>>>(emb, Wf, bf, Wb, bb);
    lstm_kernel<<<128, 256, LSTM_SMEM_BYTES>>>(tokens, Uf, Ub);
    head_kernel<<<16, 256>>>(W1, b1, W2, b2, out);
}

// round 16
// speedup vs baseline: 1.1513x; 1.0086x over previous
#include <cuda_runtime.h>
#include <cstddef>
#include <cstdint>

// Problem constants
#define BB   128     // batch
#define TT   512     // seq len
#define EE   256     // embed dim
#define HH   256     // hidden
#define G4H  1024    // 4*H
#define VV   32000   // vocab
#define NC   32      // classes

typedef unsigned long long ull;

// ---------------- device scratch (no allocations allowed) ----------------
__device__ float g_P[(size_t)VV * 2048];       // [V][2*4H] vocab projection
__device__ float g_hx[16][2][HH][16];          // [group][parity][hcol][row] h exchange
__device__ float g_hfinT[2][HH][BB];           // final hidden per direction, transposed
__device__ int   g_flag[16][8][32];            // per-(group,CTA) release flags, 128B lines

// ---------------- f32x2 helpers ----------------
__device__ __forceinline__ ull pack2(float lo, float hi) {
    ull r;
    asm("mov.b64 %0, {%1, %2};" : "=l"(r) : "f"(lo), "f"(hi));
    return r;
}
__device__ __forceinline__ float2 unpack2(ull v) {
    float2 r;
    asm("mov.b64 {%0, %1}, %2;" : "=f"(r.x), "=f"(r.y) : "l"(v));
    return r;
}
__device__ __forceinline__ void ffma2(ull& d, ull a, ull b) {
    asm("fma.rn.f32x2 %0, %1, %2, %0;" : "+l"(d) : "l"(a), "l"(b));
}
__device__ __forceinline__ void addf2(ull& d, ull a) {
    asm("add.rn.f32x2 %0, %0, %1;" : "+l"(d) : "l"(a));
}

__device__ __forceinline__ int ld_acq(const int* p) {
    int v;
    asm volatile("ld.acquire.gpu.b32 %0, [%1];" : "=r"(v) : "l"(p));
    return v;
}
__device__ __forceinline__ void st_rel(int* p, int v) {
    asm volatile("st.release.gpu.b32 [%0], %1;" :: "l"(p), "r"(v) : "memory");
}

// fast activations: single-MUFU tanh.approx; sigm via tanh identity.
__device__ __forceinline__ float ftanh(float x) {
    float r;
    asm("tanh.approx.f32 %0, %1;" : "=f"(r) : "f"(x));
    return r;
}
__device__ __forceinline__ float fsigm(float x) {
    return fmaf(ftanh(0.5f * x), 0.5f, 0.5f);
}

__device__ __forceinline__ void cpasync16(uint32_t dst, const void* src) {
    asm volatile("cp.async.cg.shared.global [%0], [%1], 16;" :: "r"(dst), "l"(src) : "memory");
}
__device__ __forceinline__ void cp_commit() {
    asm volatile("cp.async.commit_group;" ::: "memory");
}
template<int N> __device__ __forceinline__ void cp_wait() {
    asm volatile("cp.async.wait_group %0;" :: "n"(N) : "memory");
}

// =====================================================================
// Kernel A: P[v, d*1024+g] = sum_e emb[v,e] * W{f,b}[e,g] + b{f,b}[g]
// CTA 32m x 128n, 128 threads, thread tile 4m x 8n. 3-stage cp.async
// pipeline (2 compute periods cover DRAM latency), incremental pointers.
// Also resets exchange flags.
// =====================================================================
__global__ void __launch_bounds__(128) proj_kernel(
    const float* __restrict__ emb,
    const float* __restrict__ Wf, const float* __restrict__ bf,
    const float* __restrict__ Wb, const float* __restrict__ bb)
{
    if (blockIdx.x == 0 && blockIdx.y == 0 && threadIdx.x < 128)
        g_flag[threadIdx.x >> 3][threadIdx.x & 7][0] = 0;

    __shared__ float As[3][32][16];    // [stage][m][k]  2KB/stage
    __shared__ float Bs[3][16][128];   // [stage][k][n]  8KB/stage

    const int tid = threadIdx.x;
    const int tx = tid & 15, ty = tid >> 4;
    const int m0 = ty * 4, n0 = tx * 4;
    const int vbase = blockIdx.y * 32;
    const int nbase = blockIdx.x * 128;
    const int d = nbase >> 10;
    const float* W    = d ? Wb : Wf;
    const float* bias = d ? bb : bf;
    const int gbase = nbase & 1023;

    const uint32_t asA = (uint32_t)__cvta_generic_to_shared(&As[0][0][0]);
    const uint32_t asB = (uint32_t)__cvta_generic_to_shared(&Bs[0][0][0]);

    // per-thread copy coords + incremental global pointers
    const int ar = tid >> 2, aq = tid & 3;
    const uint32_t aoffT = (uint32_t)((ar * 16 + aq * 4) * 4);
    const float* aptr = emb + (size_t)(vbase + ar) * EE + aq * 4;   // += 16/stage
    const float* bptr[4];
    uint32_t boffT[4];
    #pragma unroll
    for (int j = 0; j < 4; j++) {
        int idx = tid + j * 128;
        int bk = idx >> 5, bq = idx & 31;
        bptr[j] = W + (size_t)bk * G4H + gbase + bq * 4;            // += 16*G4H/stage
        boffT[j] = (uint32_t)((bk * 128 + bq * 4) * 4);
    }

    ull acc[4][4] = {};

    // prologue: issue stages 0 and 1
    #pragma unroll
    for (int s0 = 0; s0 < 2; s0++) {
        cpasync16(asA + (uint32_t)(s0 * 2048) + aoffT, aptr);
        aptr += 16;
        #pragma unroll
        for (int j = 0; j < 4; j++) {
            cpasync16(asB + (uint32_t)(s0 * 8192) + boffT[j], bptr[j]);
            bptr[j] += 16 * G4H;
        }
        cp_commit();
    }

    int nb = 2;   // next buffer to fill
    for (int s = 0; s < 16; s++) {
        if (s + 2 < 16) {
            cpasync16(asA + (uint32_t)(nb * 2048) + aoffT, aptr);
            aptr += 16;
            #pragma unroll
            for (int j = 0; j < 4; j++) {
                cpasync16(asB + (uint32_t)(nb * 8192) + boffT[j], bptr[j]);
                bptr[j] += 16 * G4H;
            }
            cp_commit();
            nb = (nb == 2) ? 0 : nb + 1;
            cp_wait<2>();
        } else if (s + 2 == 16) {
            cp_wait<1>();
        } else {
            cp_wait<0>();
        }
        __syncthreads();

        const int b = (s < 15) ? (s % 3) : (15 % 3);
        #pragma unroll
        for (int k = 0; k < 16; k++) {
            float a0 = As[b][m0 + 0][k];
            float a1 = As[b][m0 + 1][k];
            float a2 = As[b][m0 + 2][k];
            float a3 = As[b][m0 + 3][k];
            ulonglong2 bb1 = *(const ulonglong2*)&Bs[b][k][n0];
            ulonglong2 bb2 = *(const ulonglong2*)&Bs[b][k][64 + n0];
            ull ad0 = pack2(a0, a0), ad1 = pack2(a1, a1);
            ull ad2 = pack2(a2, a2), ad3 = pack2(a3, a3);
            ffma2(acc[0][0], ad0, bb1.x); ffma2(acc[0][1], ad0, bb1.y);
            ffma2(acc[0][2], ad0, bb2.x); ffma2(acc[0][3], ad0, bb2.y);
            ffma2(acc[1][0], ad1, bb1.x); ffma2(acc[1][1], ad1, bb1.y);
            ffma2(acc[1][2], ad1, bb2.x); ffma2(acc[1][3], ad1, bb2.y);
            ffma2(acc[2][0], ad2, bb1.x); ffma2(acc[2][1], ad2, bb1.y);
            ffma2(acc[2][2], ad2, bb2.x); ffma2(acc[2][3], ad2, bb2.y);
            ffma2(acc[3][0], ad3, bb1.x); ffma2(acc[3][1], ad3, bb1.y);
            ffma2(acc[3][2], ad3, bb2.x); ffma2(acc[3][3], ad3, bb2.y);
        }
        __syncthreads();
    }

    #pragma unroll
    for (int i = 0; i < 4; i++) {
        int v = vbase + m0 + i;
        #pragma unroll
        for (int p = 0; p < 4; p++) {
            float2 va = unpack2(acc[i][p]);
            int cc = (p < 2 ? n0 + 2 * p : 64 + n0 + 2 * (p - 2));
            va.x += bias[gbase + cc];
            va.y += bias[gbase + cc + 1];
            *(float2*)&g_P[(size_t)v * 2048 + nbase + cc] = va;
        }
    }
}

// =====================================================================
// Kernel B: register-tiled 8-way-k-split LSTM, per-warp flag exchange.
// R14/R15 core; only activations changed to tanh.approx (1 MUFU each).
// =====================================================================
#define UP_BYTES   131072                     // [256 k][32 hcol] ulonglong2
#define HR_BYTES   16384                      // [256 k][16 row] float, single buf
#define RED_STRIDE 33                         // ull per thread row (32 + pad)
#define RED_BYTES  (256 * RED_STRIDE * 8)     // 67584
#define LSTM_SMEM_BYTES (UP_BYTES + HR_BYTES + RED_BYTES)   // 215040

__global__ void __launch_bounds__(256) lstm_kernel(
    const int* __restrict__ tokens,
    const float* __restrict__ Uf, const float* __restrict__ Ub)
{
    extern __shared__ char smraw[];
    ulonglong2* Up = (ulonglong2*)smraw;                     // [256 k][32 hcol]
    float* hraw = (float*)(smraw + UP_BYTES);                // [256 k][16 row]
    ull* red = (ull*)(smraw + UP_BYTES + HR_BYTES);          // [256 thr][33]
    const uint32_t hraw_addr = (uint32_t)__cvta_generic_to_shared(hraw);

    const int tid = threadIdx.x;
    const int gr  = blockIdx.x >> 3;              // group 0..15
    const int c   = blockIdx.x & 7;               // rank in group
    const int d   = gr >> 3;                      // direction
    const int rb  = (gr & 7) * 16;                // batch row base
    const float* U = d ? Ub : Uf;

    const int w    = tid >> 5;                    // warp -> k-slice [32w,32w+32)
    const int lane = tid & 31;
    const int rg   = lane & 1;                    // rows 8rg..8rg+7
    const int cg   = lane >> 1;                   // hcols {cg, cg+16}

    const int jf = tid & 31;                      // hcol within CTA
    const int q  = tid >> 5;                      // rows {2q, 2q+1}
    const int ghcol = c * 32 + jf;

    // Token dtype guard (jnp.int64 silently x32 in JAX unless x64 enabled).
    const bool is64 = ((tokens[1] | tokens[3] | tokens[5] | tokens[7]) == 0);
    const int ts = is64 ? 2 : 1;

    // Load U: Up[k][j] = { (u_i,u_f), (u_g,u_o) } at hcol c*32+j
    for (int i = tid; i < 8192; i += 256) {
        int k = i >> 5, j = i & 31;
        const float* ub = U + (size_t)k * G4H + c * 32 + j;
        ulonglong2 e;
        e.x = pack2(ub[0],   ub[256]);
        e.y = pack2(ub[512], ub[768]);
        Up[k * 32 + j] = e;
    }
    // zero h buffer (h(-1) = 0)
    for (int i = tid; i < 4096; i += 256) hraw[i] = 0.f;
    __syncthreads();

    const int* tr0 = tokens + (size_t)(rb + 2 * q + 0) * TT * ts;
    const int* tr1 = tokens + (size_t)(rb + 2 * q + 1) * TT * ts;
    const int* myPeerFlag = &g_flag[gr][w][0];
    int* myFlag = &g_flag[gr][c][0];

    // prefetch tokens for t = 0
    int te0 = d ? (TT - 1) : 0;
    int tk0 = tr0[te0 * ts], tk1 = tr1[te0 * ts];

    float cs0 = 0.f, cs1 = 0.f;

    // gather constants
    const int lane_src = 2 * (jf & 15) + (q >> 2);
    const int idx0 = ((2 * q) & 7) * 2 + (jf >> 4);

    // per-warp slice copy addresses (slice w = 2KB contiguous)
    const uint32_t slice_dst = hraw_addr + (uint32_t)(w * 2048) + (uint32_t)(lane * 16);
    const bool own_slice = (w == c);

    for (int t = 0; t < TT; t++) {
        // ---- P loads for this step (consumed after reduction) ----
        int tv0 = (tk0 >= 0 && tk0 < VV) ? tk0 : 0;
        int tv1 = (tk1 >= 0 && tk1 < VV) ? tk1 : 0;
        const float* Pb0 = g_P + (size_t)tv0 * 2048 + d * 1024 + ghcol;
        const float* Pb1 = g_P + (size_t)tv1 * 2048 + d * 1024 + ghcol;
        float p00 = Pb0[0], p01 = Pb0[256], p02 = Pb0[512], p03 = Pb0[768];
        float p10 = Pb1[0], p11 = Pb1[256], p12 = Pb1[512], p13 = Pb1[768];

        // prefetch tokens for t+1
        if (t + 1 < TT) {
            int te = d ? (TT - 2 - t) : (t + 1);
            tk0 = tr0[te * ts]; tk1 = tr1[te * ts];
        }

        // ---- per-warp: acquire peer w's h(t-1) slice (own slice is local) ----
        if (t > 0 && !own_slice) {
            while (ld_acq(myPeerFlag) < t) { }
            const char* src = (const char*)&g_hx[gr][t & 1][w * 32][0] + lane * 16;
            #pragma unroll
            for (int qq = 0; qq < 4; qq++)
                cpasync16(slice_dst + (uint32_t)(qq * 512), src + qq * 512);
            cp_commit();
            cp_wait<0>();
            __syncwarp();
        }

        // ---- k-loop over this warp's 32-k slice ----
        const ulonglong2* ub2 = Up + cg;
        ull aIF[8][2] = {}, aGO[8][2] = {};
        const int kbeg = w * 32;
        #pragma unroll 8
        for (int k = kbeg; k < kbeg + 32; k++) {
            float4 hA = *(const float4*)(hraw + k * 16 + 8 * rg);
            float4 hB = *(const float4*)(hraw + k * 16 + 8 * rg + 4);
            ulonglong2 uA = ub2[k * 32];         // hcol cg
            ulonglong2 uB = ub2[k * 32 + 16];    // hcol cg+16
            ull hd0 = pack2(hA.x, hA.x), hd1 = pack2(hA.y, hA.y);
            ull hd2 = pack2(hA.z, hA.z), hd3 = pack2(hA.w, hA.w);
            ull hd4 = pack2(hB.x, hB.x), hd5 = pack2(hB.y, hB.y);
            ull hd6 = pack2(hB.z, hB.z), hd7 = pack2(hB.w, hB.w);
            ffma2(aIF[0][0], hd0, uA.x); ffma2(aGO[0][0], hd0, uA.y);
            ffma2(aIF[0][1], hd0, uB.x); ffma2(aGO[0][1], hd0, uB.y);
            ffma2(aIF[1][0], hd1, uA.x); ffma2(aGO[1][0], hd1, uA.y);
            ffma2(aIF[1][1], hd1, uB.x); ffma2(aGO[1][1], hd1, uB.y);
            ffma2(aIF[2][0], hd2, uA.x); ffma2(aGO[2][0], hd2, uA.y);
            ffma2(aIF[2][1], hd2, uB.x); ffma2(aGO[2][1], hd2, uB.y);
            ffma2(aIF[3][0], hd3, uA.x); ffma2(aGO[3][0], hd3, uA.y);
            ffma2(aIF[3][1], hd3, uB.x); ffma2(aGO[3][1], hd3, uB.y);
            ffma2(aIF[4][0], hd4, uA.x); ffma2(aGO[4][0], hd4, uA.y);
            ffma2(aIF[4][1], hd4, uB.x); ffma2(aGO[4][1], hd4, uB.y);
            ffma2(aIF[5][0], hd5, uA.x); ffma2(aGO[5][0], hd5, uA.y);
            ffma2(aIF[5][1], hd5, uB.x); ffma2(aGO[5][1], hd5, uB.y);
            ffma2(aIF[6][0], hd6, uA.x); ffma2(aGO[6][0], hd6, uA.y);
            ffma2(aIF[6][1], hd6, uB.x); ffma2(aGO[6][1], hd6, uB.y);
            ffma2(aIF[7][0], hd7, uA.x); ffma2(aGO[7][0], hd7, uA.y);
            ffma2(aIF[7][1], hd7, uB.x); ffma2(aGO[7][1], hd7, uB.y);
        }

        // ---- merged reduction: store IF+GO partials, one sync, one gather ----
        ull* myred = red + tid * RED_STRIDE;
        #pragma unroll
        for (int i = 0; i < 8; i++) {
            myred[2 * i]          = aIF[i][0];
            myred[2 * i + 1]      = aIF[i][1];
            myred[16 + 2 * i]     = aGO[i][0];
            myred[16 + 2 * i + 1] = aGO[i][1];
        }
        __syncthreads();
        ull zIF0 = 0ull, zIF1 = 0ull, zGO0 = 0ull, zGO1 = 0ull;
        #pragma unroll
        for (int w8 = 0; w8 < 8; w8++) {
            const ull* pr = red + (w8 * 32 + lane_src) * RED_STRIDE;
            addf2(zIF0, pr[idx0]);
            addf2(zIF1, pr[idx0 + 2]);
            addf2(zGO0, pr[16 + idx0]);
            addf2(zGO1, pr[16 + idx0 + 2]);
        }

        // ---- activation (rows 2q, 2q+1; hcol jf) ----
        float2 vIF0 = unpack2(zIF0), vGO0 = unpack2(zGO0);
        float2 vIF1 = unpack2(zIF1), vGO1 = unpack2(zGO1);
        float i0 = fsigm(vIF0.x + p00), f0 = fsigm(vIF0.y + p01);
        float g0 = ftanh(vGO0.x + p02), o0 = fsigm(vGO0.y + p03);
        float i1 = fsigm(vIF1.x + p10), f1 = fsigm(vIF1.y + p11);
        float g1 = ftanh(vGO1.x + p12), o1 = fsigm(vGO1.y + p13);
        cs0 = f0 * cs0 + i0 * g0;
        cs1 = f1 * cs1 + i1 * g1;
        float h0 = o0 * ftanh(cs0);
        float h1 = o1 * ftanh(cs1);

        if (t == TT - 1) {
            *(float2*)&g_hfinT[d][ghcol][rb + 2 * q] = make_float2(h0, h1);
        } else {
            // publish h(t): global for peers + local STS for own warp c's slice
            *(float2*)&g_hx[gr][(t + 1) & 1][ghcol][2 * q] = make_float2(h0, h1);
            *(float2*)&hraw[(c * 32 + jf) * 16 + 2 * q] = make_float2(h0, h1);
            __syncthreads();                       // all CTA stores issued; red reusable
            if (tid == 0) st_rel(myFlag, t + 1);   // release: publishes CTA's h
        }
    }
}

// =====================================================================
// Kernel C: head.  h1 = relu([hf|hb] @ W1 + b1); out = softmax(h1 @ W2 + b2)
// =====================================================================
__global__ void __launch_bounds__(256) head_kernel(
    const float* __restrict__ W1, const float* __restrict__ b1,
    const float* __restrict__ W2, const float* __restrict__ b2,
    float* __restrict__ out)
{
    __shared__ float hc[8][512];
    __shared__ float h1[8][256];

    const int tid = threadIdx.x;
    const int rb = blockIdx.x * 8;

    for (int i = tid; i < 4096; i += 256) {
        int rr = i >> 9, k = i & 511;
        int dd = k >> 8, kk = k & 255;
        hc[rr][k] = g_hfinT[dd][kk][rb + rr];
    }
    __syncthreads();

    const int jj = tid;
    float acc[8] = {0.f, 0.f, 0.f, 0.f, 0.f, 0.f, 0.f, 0.f};
    for (int k = 0; k < 512; k++) {
        float wv = W1[(size_t)k * HH + jj];
        #pragma unroll
        for (int rr = 0; rr < 8; rr++) acc[rr] += hc[rr][k] * wv;
    }
    float bj = b1[jj];
    #pragma unroll
    for (int rr = 0; rr < 8; rr++) h1[rr][jj] = fmaxf(acc[rr] + bj, 0.f);
    __syncthreads();

    const int rr = tid >> 5, cc = tid & 31;
    float l = b2[cc];
    for (int k = 0; k < HH; k++) l += h1[rr][k] * W2[(size_t)k * NC + cc];

    float m = l;
    #pragma unroll
    for (int o = 16; o > 0; o >>= 1) m = fmaxf(m, __shfl_xor_sync(0xffffffffu, m, o));
    float e = expf(l - m);
    float ssum = e;
    #pragma unroll
    for (int o = 16; o > 0; o >>= 1) ssum += __shfl_xor_sync(0xffffffffu, ssum, o);
    out[(size_t)(rb + rr) * NC + cc] = e / ssum;
}

// =====================================================================
extern "C" void kernel_launch(void* const* d_in, const int* in_sizes, int n_in,
                              void* d_out, int out_size)
{
    const int*   tokens = (const int*)d_in[0];
    const float* emb = (const float*)d_in[1];
    const float* Wf  = (const float*)d_in[2];
    const float* Uf  = (const float*)d_in[3];
    const float* bf  = (const float*)d_in[4];
    const float* Wb  = (const float*)d_in[5];
    const float* Ub  = (const float*)d_in[6];
    const float* bb  = (const float*)d_in[7];
    const float* W1  = (const float*)d_in[8];
    const float* b1  = (const float*)d_in[9];
    const float* W2  = (const float*)d_in[10];
    const float* b2  = (const float*)d_in[11];
    float* out = (float*)d_out;

    cudaFuncSetAttribute(lstm_kernel, cudaFuncAttributeMaxDynamicSharedMemorySize, LSTM_SMEM_BYTES);

    proj_kernel<<<dim3(16, 1000), 128>>>(emb, Wf, bf, Wb, bb);
    lstm_kernel<<<128, 256, LSTM_SMEM_BYTES>>>(tokens, Uf, Ub);
    head_kernel<<<16, 256>>>(W1, b1, W2, b2, out);
}